// round 1
// baseline (speedup 1.0000x reference)
#include <cuda_runtime.h>
#include <math.h>

#define NN 50000
#define EE 500000
#define HH 128
#define NHH 8
// DH = 16, scale = 0.25

// ---------------- scratch (device globals; no runtime alloc) ----------------
__device__ float g_buf1[(size_t)NN * 256];  // gin hidden (N,128) then FFN hidden (N,256)
__device__ float g_agg [(size_t)NN * HH];   // edge agg -> gin2 out -> xl (in-place)
__device__ float g_q   [(size_t)NN * HH];
__device__ float g_k   [(size_t)NN * HH];
__device__ float g_v   [(size_t)NN * HH];
__device__ float g_ao  [(size_t)NN * HH];   // attn out -> xa (in-place)
__device__ float g_hc  [(size_t)NN * HH];   // combine -> +FFN (in-place)
__device__ float g_p   [(size_t)EE * NHH];  // exp(scores)
__device__ float g_den [(size_t)NN * NHH];
__device__ float g_sum  [3][HH];
__device__ float g_sumsq[3][HH];
__device__ float g_bnA  [3][HH];
__device__ float g_bnB  [3][HH];

// ---------------- small helpers ----------------
__device__ __forceinline__ void red4(float* p, float4 v) {
    asm volatile("red.global.add.v4.f32 [%0], {%1,%2,%3,%4};"
                 :: "l"(p), "f"(v.x), "f"(v.y), "f"(v.z), "f"(v.w) : "memory");
}

__global__ void k_zero(float* __restrict__ p, size_t n) {
    size_t i = (size_t)blockIdx.x * blockDim.x + threadIdx.x;
    size_t st = (size_t)gridDim.x * blockDim.x;
    for (; i < n; i += st) p[i] = 0.f;
}

__global__ void k_copy4(const float4* __restrict__ s, float4* __restrict__ d, size_t n4) {
    size_t i = (size_t)blockIdx.x * blockDim.x + threadIdx.x;
    size_t st = (size_t)gridDim.x * blockDim.x;
    for (; i < n4; i += st) d[i] = s[i];
}

// ---------------- edge kernels (1 warp per edge, float4 per lane) ----------------
__global__ void k_edge_agg(const float* __restrict__ h, const float* __restrict__ ea,
                           const int* __restrict__ src, const int* __restrict__ dst,
                           float* __restrict__ agg) {
    int e = blockIdx.x * 8 + (threadIdx.x >> 5);
    if (e >= EE) return;
    int lane = threadIdx.x & 31;
    int s = src[e], d = dst[e];
    float4 hv = *(const float4*)(h  + (size_t)s * HH + lane * 4);
    float4 ev = *(const float4*)(ea + (size_t)e * HH + lane * 4);
    float4 m;
    m.x = fmaxf(hv.x + ev.x, 0.f);
    m.y = fmaxf(hv.y + ev.y, 0.f);
    m.z = fmaxf(hv.z + ev.z, 0.f);
    m.w = fmaxf(hv.w + ev.w, 0.f);
    red4(agg + (size_t)d * HH + lane * 4, m);
}

// per-edge per-head scores; softmax max-subtraction skipped (scores ~O(0.1))
__global__ void k_edge_score(const float* __restrict__ q, const float* __restrict__ k,
                             const int* __restrict__ src, const int* __restrict__ dst,
                             float* __restrict__ p, float* __restrict__ den) {
    int e = blockIdx.x * 8 + (threadIdx.x >> 5);
    if (e >= EE) return;
    int lane = threadIdx.x & 31;
    int s = src[e], d = dst[e];
    float4 qv = *(const float4*)(q + (size_t)s * HH + lane * 4);
    float4 kv = *(const float4*)(k + (size_t)d * HH + lane * 4);
    float part = qv.x * kv.x + qv.y * kv.y + qv.z * kv.z + qv.w * kv.w;
    part += __shfl_xor_sync(0xffffffffu, part, 1);
    part += __shfl_xor_sync(0xffffffffu, part, 2);
    if ((lane & 3) == 0) {
        int hd = lane >> 2;
        float pe = expf(part);
        p[(size_t)e * NHH + hd] = pe;
        atomicAdd(&den[(size_t)s * NHH + hd], pe);
    }
}

__global__ void k_edge_out(const float* __restrict__ p, const float* __restrict__ den,
                           const float* __restrict__ v,
                           const int* __restrict__ src, const int* __restrict__ dst,
                           float* __restrict__ ao) {
    int e = blockIdx.x * 8 + (threadIdx.x >> 5);
    if (e >= EE) return;
    int lane = threadIdx.x & 31;
    int s = src[e], d = dst[e];
    int hd = lane >> 2;
    float w = p[(size_t)e * NHH + hd] / den[(size_t)s * NHH + hd];
    float4 vv = *(const float4*)(v + (size_t)d * HH + lane * 4);
    float4 m;
    m.x = w * vv.x; m.y = w * vv.y; m.z = w * vv.z; m.w = w * vv.w;
    red4(ao + (size_t)s * HH + lane * 4, m);
}

// ---------------- SIMT fp32 GEMM: C[M,Nc] = act( (A[+A2]) @ W^T + bias )*scale [+res] ---------
// W row-major [Nc,K]. 128x128 tile, K-chunks of 32, 256 threads, 8x8 microtile.
__global__ __launch_bounds__(256) void k_gemm(
    const float* __restrict__ A, const float* __restrict__ A2,
    const float* __restrict__ W, const float* __restrict__ bias,
    const float* __restrict__ res, float* __restrict__ C,
    int M, int Nc, int K, float scale, int do_relu)
{
    __shared__ float As[128][33];
    __shared__ float Bs[128][33];
    int m0 = blockIdx.x * 128;
    int n0 = blockIdx.y * 128;
    int tid = threadIdx.x;
    int tx = tid & 15, ty = tid >> 4;
    float acc[8][8];
#pragma unroll
    for (int i = 0; i < 8; i++)
#pragma unroll
        for (int j = 0; j < 8; j++) acc[i][j] = 0.f;

    for (int k0 = 0; k0 < K; k0 += 32) {
#pragma unroll
        for (int i = 0; i < 16; i++) {
            int idx = tid + i * 256;          // 0..4095
            int r = idx >> 5, c = idx & 31;
            int gm = m0 + r;
            float va = 0.f;
            if (gm < M) {
                va = A[(size_t)gm * K + k0 + c];
                if (A2) va += A2[(size_t)gm * K + k0 + c];
            }
            As[r][c] = va;
        }
#pragma unroll
        for (int i = 0; i < 16; i++) {
            int idx = tid + i * 256;
            int r = idx >> 5, c = idx & 31;
            Bs[r][c] = W[(size_t)(n0 + r) * K + k0 + c];
        }
        __syncthreads();
#pragma unroll
        for (int kk = 0; kk < 32; kk++) {
            float a[8], b[8];
#pragma unroll
            for (int i = 0; i < 8; i++) a[i] = As[ty * 8 + i][kk];
#pragma unroll
            for (int j = 0; j < 8; j++) b[j] = Bs[tx + 16 * j][kk];
#pragma unroll
            for (int i = 0; i < 8; i++)
#pragma unroll
                for (int j = 0; j < 8; j++) acc[i][j] = fmaf(a[i], b[j], acc[i][j]);
        }
        __syncthreads();
    }
#pragma unroll
    for (int i = 0; i < 8; i++) {
        int gm = m0 + ty * 8 + i;
        if (gm >= M) continue;
#pragma unroll
        for (int j = 0; j < 8; j++) {
            int gn = n0 + tx + 16 * j;
            float vv = (acc[i][j] + bias[gn]) * scale;
            if (do_relu) vv = fmaxf(vv, 0.f);
            if (res) vv += res[(size_t)gm * Nc + gn];
            C[(size_t)gm * Nc + gn] = vv;
        }
    }
}

// ---------------- BN stats: out = a (+ b), accumulate per-feature sums ----------------
__global__ void k_addstats(const float* __restrict__ a, const float* __restrict__ b,
                           float* __restrict__ out, float* __restrict__ sum,
                           float* __restrict__ sumsq) {
    __shared__ float ssum[256], ssq[256];
    int c = threadIdx.x & 127;
    int half = threadIdx.x >> 7;
    int rowsPerBlock = (NN + gridDim.x - 1) / gridDim.x;
    int r0 = blockIdx.x * rowsPerBlock;
    int r1 = min(r0 + rowsPerBlock, NN);
    float ps = 0.f, pq = 0.f;
    for (int r = r0 + half; r < r1; r += 2) {
        size_t idx = (size_t)r * HH + c;
        float v = a[idx];
        if (b) v += b[idx];
        if (out) out[idx] = v;
        ps += v; pq += v * v;
    }
    ssum[threadIdx.x] = ps; ssq[threadIdx.x] = pq;
    __syncthreads();
    if (threadIdx.x < 128) {
        atomicAdd(&sum[c],   ssum[threadIdx.x] + ssum[threadIdx.x + 128]);
        atomicAdd(&sumsq[c], ssq[threadIdx.x]  + ssq[threadIdx.x + 128]);
    }
}

__global__ void k_bnfin(int which, const float* __restrict__ g, const float* __restrict__ b) {
    int c = threadIdx.x;
    float mean = g_sum[which][c] * (1.f / NN);
    float var  = g_sumsq[which][c] * (1.f / NN) - mean * mean;
    float a = g[c] * rsqrtf(var + 1e-5f);
    g_bnA[which][c] = a;
    g_bnB[which][c] = b[c] - mean * a;
}

// hc = bn0(xl) + bn1(xa)
__global__ void k_combine(const float* __restrict__ xl, const float* __restrict__ xa,
                          float* __restrict__ hc) {
    size_t i = (size_t)blockIdx.x * blockDim.x + threadIdx.x;  // float4 index
    if (i >= (size_t)NN * 32) return;
    int c4 = (int)(i & 31);
    float4 xlv = ((const float4*)xl)[i];
    float4 xav = ((const float4*)xa)[i];
    float4 a0 = *(const float4*)&g_bnA[0][c4 * 4];
    float4 b0 = *(const float4*)&g_bnB[0][c4 * 4];
    float4 a1 = *(const float4*)&g_bnA[1][c4 * 4];
    float4 b1 = *(const float4*)&g_bnB[1][c4 * 4];
    float4 o;
    o.x = a0.x * xlv.x + b0.x + a1.x * xav.x + b1.x;
    o.y = a0.y * xlv.y + b0.y + a1.y * xav.y + b1.y;
    o.z = a0.z * xlv.z + b0.z + a1.z * xav.z + b1.z;
    o.w = a0.w * xlv.w + b0.w + a1.w * xav.w + b1.w;
    ((float4*)hc)[i] = o;
}

// out = bn2(hc)
__global__ void k_apply(const float* __restrict__ hc, float* __restrict__ out) {
    size_t i = (size_t)blockIdx.x * blockDim.x + threadIdx.x;
    if (i >= (size_t)NN * 32) return;
    int c4 = (int)(i & 31);
    float4 xv = ((const float4*)hc)[i];
    float4 a2 = *(const float4*)&g_bnA[2][c4 * 4];
    float4 b2 = *(const float4*)&g_bnB[2][c4 * 4];
    float4 o;
    o.x = a2.x * xv.x + b2.x;
    o.y = a2.y * xv.y + b2.y;
    o.z = a2.z * xv.z + b2.z;
    o.w = a2.w * xv.w + b2.w;
    ((float4*)out)[i] = o;
}

// ---------------- launcher ----------------
extern "C" void kernel_launch(void* const* d_in, const int* in_sizes, int n_in,
                              void* d_out, int out_size) {
    const float* h      = (const float*)d_in[0];
    const float* eattr  = (const float*)d_in[1];
    const int*   src    = (const int*)d_in[2];
    const int*   dst    = (const int*)d_in[3];
    const float* gin_w1 = (const float*)d_in[4];
    const float* gin_b1 = (const float*)d_in[5];
    const float* gin_w2 = (const float*)d_in[6];
    const float* gin_b2 = (const float*)d_in[7];
    const float* wq = (const float*)d_in[8];
    const float* bq = (const float*)d_in[9];
    const float* wk = (const float*)d_in[10];
    const float* bk = (const float*)d_in[11];
    const float* wv = (const float*)d_in[12];
    const float* bv = (const float*)d_in[13];
    const float* nl_g = (const float*)d_in[14];
    const float* nl_b = (const float*)d_in[15];
    const float* na_g = (const float*)d_in[16];
    const float* na_b = (const float*)d_in[17];
    const float* no_g = (const float*)d_in[18];
    const float* no_b = (const float*)d_in[19];
    const float* ffn1_w = (const float*)d_in[20];
    const float* ffn1_b = (const float*)d_in[21];
    const float* ffn2_w = (const float*)d_in[22];
    const float* ffn2_b = (const float*)d_in[23];

    float* out_hc = (float*)d_out;
    float* out_ea = (float*)d_out + (size_t)NN * HH;

    float *p_buf1, *p_agg, *p_q, *p_k, *p_v, *p_ao, *p_hc, *p_p, *p_den, *p_sum, *p_sumsq;
    cudaGetSymbolAddress((void**)&p_buf1, g_buf1);
    cudaGetSymbolAddress((void**)&p_agg,  g_agg);
    cudaGetSymbolAddress((void**)&p_q,    g_q);
    cudaGetSymbolAddress((void**)&p_k,    g_k);
    cudaGetSymbolAddress((void**)&p_v,    g_v);
    cudaGetSymbolAddress((void**)&p_ao,   g_ao);
    cudaGetSymbolAddress((void**)&p_hc,   g_hc);
    cudaGetSymbolAddress((void**)&p_p,    g_p);
    cudaGetSymbolAddress((void**)&p_den,  g_den);
    cudaGetSymbolAddress((void**)&p_sum,  g_sum);
    cudaGetSymbolAddress((void**)&p_sumsq, g_sumsq);

    const int EB = (EE + 7) / 8;      // edge kernels: 8 warps/block
    const int MB = (NN + 127) / 128;  // gemm row tiles

    // zero scratch that gets atomically accumulated
    k_zero<<<1024, 256>>>(p_agg, (size_t)NN * HH);
    k_zero<<<1024, 256>>>(p_ao,  (size_t)NN * HH);
    k_zero<<<256, 256>>>(p_den, (size_t)NN * NHH);
    k_zero<<<2, 256>>>(p_sum, 3 * HH);
    k_zero<<<2, 256>>>(p_sumsq, 3 * HH);

    // eattr passthrough
    k_copy4<<<65536, 256>>>((const float4*)eattr, (float4*)out_ea, (size_t)EE * HH / 4);

    // --- local branch: GINEConv ---
    k_edge_agg<<<EB, 256>>>(h, eattr, src, dst, p_agg);
    // t1 = relu((h+agg) @ gin_w1^T + gin_b1)
    k_gemm<<<dim3(MB, 1), 256>>>(h, p_agg, gin_w1, gin_b1, nullptr, p_buf1,
                                 NN, HH, HH, 1.f, 1);
    // h_local = t1 @ gin_w2^T + gin_b2   (into g_agg, reuse)
    k_gemm<<<dim3(MB, 1), 256>>>(p_buf1, nullptr, gin_w2, gin_b2, nullptr, p_agg,
                                 NN, HH, HH, 1.f, 0);
    // xl = h + h_local (in-place in g_agg), stats set 0
    k_addstats<<<256, 256>>>(h, p_agg, p_agg, &p_sum[0 * HH], &p_sumsq[0 * HH]);

    // --- global branch: sparse MHA ---
    k_gemm<<<dim3(MB, 1), 256>>>(h, nullptr, wq, bq, nullptr, p_q, NN, HH, HH, 0.25f, 0);
    k_gemm<<<dim3(MB, 1), 256>>>(h, nullptr, wk, bk, nullptr, p_k, NN, HH, HH, 1.f, 0);
    k_gemm<<<dim3(MB, 1), 256>>>(h, nullptr, wv, bv, nullptr, p_v, NN, HH, HH, 1.f, 0);
    k_edge_score<<<EB, 256>>>(p_q, p_k, src, dst, p_p, p_den);
    k_edge_out<<<EB, 256>>>(p_p, p_den, p_v, src, dst, p_ao);
    // xa = h + attn_out (in-place in g_ao), stats set 1
    k_addstats<<<256, 256>>>(h, p_ao, p_ao, &p_sum[1 * HH], &p_sumsq[1 * HH]);

    // finalize BNs 0 and 1, combine
    k_bnfin<<<1, 128>>>(0, nl_g, nl_b);
    k_bnfin<<<1, 128>>>(1, na_g, na_b);
    k_combine<<<(NN * 32 + 255) / 256, 256>>>(p_agg, p_ao, p_hc);

    // --- FFN ---
    // f = relu(hc @ ffn1_w^T + ffn1_b)  [N,256]
    k_gemm<<<dim3(MB, 2), 256>>>(p_hc, nullptr, ffn1_w, ffn1_b, nullptr, p_buf1,
                                 NN, 256, HH, 1.f, 1);
    // hc = hc + f @ ffn2_w^T + ffn2_b  (in-place residual)
    k_gemm<<<dim3(MB, 1), 256>>>(p_buf1, nullptr, ffn2_w, ffn2_b, p_hc, p_hc,
                                 NN, HH, 256, 1.f, 0);
    // stats set 2 (no add, no out)
    k_addstats<<<256, 256>>>(p_hc, nullptr, nullptr, &p_sum[2 * HH], &p_sumsq[2 * HH]);
    k_bnfin<<<1, 128>>>(2, no_g, no_b);
    k_apply<<<(NN * 32 + 255) / 256, 256>>>(p_hc, out_hc);
}

// round 2
// speedup vs baseline: 1.7751x; 1.7751x over previous
#include <cuda_runtime.h>
#include <math.h>

#define NN 50000
#define EE 500000
#define HH 128
#define NHH 8
// DH = 16, scale = 0.25

// ---------------- scratch (device globals; no runtime alloc) ----------------
__device__ float g_buf1[(size_t)NN * 256];  // gin hidden (N,128) then FFN hidden (N,256)
__device__ float g_agg [(size_t)NN * HH];   // edge agg -> gin2 out -> xl (in-place)
__device__ float g_q   [(size_t)NN * HH];
__device__ float g_k   [(size_t)NN * HH];
__device__ float g_v   [(size_t)NN * HH];
__device__ float g_ao  [(size_t)NN * HH];   // attn out -> xa (in-place)
__device__ float g_hc  [(size_t)NN * HH];   // combine -> +FFN (in-place)
__device__ float g_p   [(size_t)EE * NHH];  // exp(scores)
__device__ float g_den [(size_t)NN * NHH];
__device__ float g_sum  [3][HH];
__device__ float g_sumsq[3][HH];
__device__ float g_bnA  [3][HH];
__device__ float g_bnB  [3][HH];

// ---------------- small helpers ----------------
__device__ __forceinline__ void red4(float* p, float4 v) {
    asm volatile("red.global.add.v4.f32 [%0], {%1,%2,%3,%4};"
                 :: "l"(p), "f"(v.x), "f"(v.y), "f"(v.z), "f"(v.w) : "memory");
}

__device__ __forceinline__ unsigned f2tf32(float f) {
    unsigned u;
    asm("cvt.rna.tf32.f32 %0, %1;" : "=r"(u) : "f"(f));
    return u;
}

// ---------------- edge kernels (1 warp per edge, float4 per lane) ----------------
// also writes the eattr passthrough output (fused copy)
__global__ void k_edge_agg(const float* __restrict__ h, const float* __restrict__ ea,
                           const int* __restrict__ src, const int* __restrict__ dst,
                           float* __restrict__ agg, float* __restrict__ ea_out) {
    int e = blockIdx.x * 8 + (threadIdx.x >> 5);
    if (e >= EE) return;
    int lane = threadIdx.x & 31;
    int s = src[e], d = dst[e];
    float4 hv = *(const float4*)(h  + (size_t)s * HH + lane * 4);
    float4 ev = *(const float4*)(ea + (size_t)e * HH + lane * 4);
    *(float4*)(ea_out + (size_t)e * HH + lane * 4) = ev;   // passthrough
    float4 m;
    m.x = fmaxf(hv.x + ev.x, 0.f);
    m.y = fmaxf(hv.y + ev.y, 0.f);
    m.z = fmaxf(hv.z + ev.z, 0.f);
    m.w = fmaxf(hv.w + ev.w, 0.f);
    red4(agg + (size_t)d * HH + lane * 4, m);
}

// per-edge per-head scores; softmax max-subtraction skipped (scores ~O(0.1))
__global__ void k_edge_score(const float* __restrict__ q, const float* __restrict__ k,
                             const int* __restrict__ src, const int* __restrict__ dst,
                             float* __restrict__ p, float* __restrict__ den) {
    int e = blockIdx.x * 8 + (threadIdx.x >> 5);
    if (e >= EE) return;
    int lane = threadIdx.x & 31;
    int s = src[e], d = dst[e];
    float4 qv = *(const float4*)(q + (size_t)s * HH + lane * 4);
    float4 kv = *(const float4*)(k + (size_t)d * HH + lane * 4);
    float part = qv.x * kv.x + qv.y * kv.y + qv.z * kv.z + qv.w * kv.w;
    part += __shfl_xor_sync(0xffffffffu, part, 1);
    part += __shfl_xor_sync(0xffffffffu, part, 2);
    if ((lane & 3) == 0) {
        int hd = lane >> 2;
        float pe = expf(part);
        p[(size_t)e * NHH + hd] = pe;
        atomicAdd(&den[(size_t)s * NHH + hd], pe);
    }
}

__global__ void k_edge_out(const float* __restrict__ p, const float* __restrict__ den,
                           const float* __restrict__ v,
                           const int* __restrict__ src, const int* __restrict__ dst,
                           float* __restrict__ ao) {
    int e = blockIdx.x * 8 + (threadIdx.x >> 5);
    if (e >= EE) return;
    int lane = threadIdx.x & 31;
    int s = src[e], d = dst[e];
    int hd = lane >> 2;
    float w = p[(size_t)e * NHH + hd] / den[(size_t)s * NHH + hd];
    float4 vv = *(const float4*)(v + (size_t)d * HH + lane * 4);
    float4 m;
    m.x = w * vv.x; m.y = w * vv.y; m.z = w * vv.z; m.w = w * vv.w;
    red4(ao + (size_t)s * HH + lane * 4, m);
}

// ---------------- TF32 tensor-core GEMM ----------------
// C[M,Nc] = act( ((A[+A2]) @ W^T + bias) * scale ) [+res]
// W row-major [Nc,K]. Block tile 128x128, K chunked by 32.
// 8 warps: 4 (M) x 2 (N); warp tile 32x64 via m16n8k8 tf32 mma.
__global__ __launch_bounds__(256) void k_gemm_tc(
    const float* __restrict__ A, const float* __restrict__ A2,
    const float* __restrict__ W, const float* __restrict__ bias,
    const float* __restrict__ res, float* __restrict__ C,
    int M, int Nc, int K, float scale, int do_relu)
{
    __shared__ unsigned As[128][36];
    __shared__ unsigned Bs[128][36];
    const int m0 = blockIdx.x * 128;
    const int n0 = blockIdx.y * 128;
    const int tid = threadIdx.x;
    const int wid = tid >> 5;
    const int lane = tid & 31;
    const int g = lane >> 2;       // groupID
    const int t = lane & 3;        // threadID_in_group
    const int wm = wid >> 1;       // 0..3, rows wm*32..
    const int wn = wid & 1;        // 0..1, cols wn*64..

    float acc[2][8][4];
#pragma unroll
    for (int mt = 0; mt < 2; mt++)
#pragma unroll
        for (int nt = 0; nt < 8; nt++)
#pragma unroll
            for (int c = 0; c < 4; c++) acc[mt][nt][c] = 0.f;

    for (int k0 = 0; k0 < K; k0 += 32) {
        // stage A and W chunks (convert to tf32 once)
#pragma unroll
        for (int i = 0; i < 4; i++) {
            int idx = tid + i * 256;          // 0..1023 float4 slots
            int r = idx >> 3;
            int c4 = (idx & 7) * 4;
            int gm = m0 + r;
            float4 va = make_float4(0.f, 0.f, 0.f, 0.f);
            if (gm < M) {
                va = *(const float4*)(A + (size_t)gm * K + k0 + c4);
                if (A2) {
                    float4 v2 = *(const float4*)(A2 + (size_t)gm * K + k0 + c4);
                    va.x += v2.x; va.y += v2.y; va.z += v2.z; va.w += v2.w;
                }
            }
            As[r][c4 + 0] = f2tf32(va.x);
            As[r][c4 + 1] = f2tf32(va.y);
            As[r][c4 + 2] = f2tf32(va.z);
            As[r][c4 + 3] = f2tf32(va.w);
            float4 vb = *(const float4*)(W + (size_t)(n0 + r) * K + k0 + c4);
            Bs[r][c4 + 0] = f2tf32(vb.x);
            Bs[r][c4 + 1] = f2tf32(vb.y);
            Bs[r][c4 + 2] = f2tf32(vb.z);
            Bs[r][c4 + 3] = f2tf32(vb.w);
        }
        __syncthreads();

#pragma unroll
        for (int ks = 0; ks < 4; ks++) {
            const int kb = ks * 8;
            unsigned a[2][4];
#pragma unroll
            for (int mt = 0; mt < 2; mt++) {
                int r = wm * 32 + mt * 16 + g;
                a[mt][0] = As[r][kb + t];
                a[mt][1] = As[r + 8][kb + t];
                a[mt][2] = As[r][kb + t + 4];
                a[mt][3] = As[r + 8][kb + t + 4];
            }
            unsigned b[8][2];
#pragma unroll
            for (int nt = 0; nt < 8; nt++) {
                int r = wn * 64 + nt * 8 + g;
                b[nt][0] = Bs[r][kb + t];
                b[nt][1] = Bs[r][kb + t + 4];
            }
#pragma unroll
            for (int mt = 0; mt < 2; mt++)
#pragma unroll
                for (int nt = 0; nt < 8; nt++) {
                    asm volatile(
                        "mma.sync.aligned.m16n8k8.row.col.f32.tf32.tf32.f32 "
                        "{%0,%1,%2,%3}, {%4,%5,%6,%7}, {%8,%9}, {%0,%1,%2,%3};"
                        : "+f"(acc[mt][nt][0]), "+f"(acc[mt][nt][1]),
                          "+f"(acc[mt][nt][2]), "+f"(acc[mt][nt][3])
                        : "r"(a[mt][0]), "r"(a[mt][1]), "r"(a[mt][2]), "r"(a[mt][3]),
                          "r"(b[nt][0]), "r"(b[nt][1]));
                }
        }
        __syncthreads();
    }

    // epilogue: c0,c1 at (row, 2t), c2,c3 at (row+8, 2t)
#pragma unroll
    for (int mt = 0; mt < 2; mt++) {
#pragma unroll
        for (int nt = 0; nt < 8; nt++) {
            int row = m0 + wm * 32 + mt * 16 + g;
            int gn = n0 + wn * 64 + nt * 8 + 2 * t;
            float b0 = bias[gn], b1 = bias[gn + 1];
            if (row < M) {
                float v0 = (acc[mt][nt][0] + b0) * scale;
                float v1 = (acc[mt][nt][1] + b1) * scale;
                if (do_relu) { v0 = fmaxf(v0, 0.f); v1 = fmaxf(v1, 0.f); }
                if (res) {
                    float2 rv = *(const float2*)(res + (size_t)row * Nc + gn);
                    v0 += rv.x; v1 += rv.y;
                }
                *(float2*)(C + (size_t)row * Nc + gn) = make_float2(v0, v1);
            }
            int row2 = row + 8;
            if (row2 < M) {
                float v2 = (acc[mt][nt][2] + b0) * scale;
                float v3 = (acc[mt][nt][3] + b1) * scale;
                if (do_relu) { v2 = fmaxf(v2, 0.f); v3 = fmaxf(v3, 0.f); }
                if (res) {
                    float2 rv = *(const float2*)(res + (size_t)row2 * Nc + gn);
                    v2 += rv.x; v3 += rv.y;
                }
                *(float2*)(C + (size_t)row2 * Nc + gn) = make_float2(v2, v3);
            }
        }
    }
}

// ---------------- BN stats: out = a (+ b), accumulate per-feature sums ----------------
__global__ void k_addstats(const float* __restrict__ a, const float* __restrict__ b,
                           float* __restrict__ out, float* __restrict__ sum,
                           float* __restrict__ sumsq) {
    __shared__ float ssum[256], ssq[256];
    int c = threadIdx.x & 127;
    int half = threadIdx.x >> 7;
    int rowsPerBlock = (NN + gridDim.x - 1) / gridDim.x;
    int r0 = blockIdx.x * rowsPerBlock;
    int r1 = min(r0 + rowsPerBlock, NN);
    float ps = 0.f, pq = 0.f;
    for (int r = r0 + half; r < r1; r += 2) {
        size_t idx = (size_t)r * HH + c;
        float v = a[idx];
        if (b) v += b[idx];
        if (out) out[idx] = v;
        ps += v; pq += v * v;
    }
    ssum[threadIdx.x] = ps; ssq[threadIdx.x] = pq;
    __syncthreads();
    if (threadIdx.x < 128) {
        atomicAdd(&sum[c],   ssum[threadIdx.x] + ssum[threadIdx.x + 128]);
        atomicAdd(&sumsq[c], ssq[threadIdx.x]  + ssq[threadIdx.x + 128]);
    }
}

__global__ void k_bnfin(int which, const float* __restrict__ g, const float* __restrict__ b) {
    int c = threadIdx.x;
    float mean = g_sum[which][c] * (1.f / NN);
    float var  = g_sumsq[which][c] * (1.f / NN) - mean * mean;
    float a = g[c] * rsqrtf(var + 1e-5f);
    g_bnA[which][c] = a;
    g_bnB[which][c] = b[c] - mean * a;
}

// hc = bn0(xl) + bn1(xa)
__global__ void k_combine(const float* __restrict__ xl, const float* __restrict__ xa,
                          float* __restrict__ hc) {
    size_t i = (size_t)blockIdx.x * blockDim.x + threadIdx.x;  // float4 index
    if (i >= (size_t)NN * 32) return;
    int c4 = (int)(i & 31);
    float4 xlv = ((const float4*)xl)[i];
    float4 xav = ((const float4*)xa)[i];
    float4 a0 = *(const float4*)&g_bnA[0][c4 * 4];
    float4 b0 = *(const float4*)&g_bnB[0][c4 * 4];
    float4 a1 = *(const float4*)&g_bnA[1][c4 * 4];
    float4 b1 = *(const float4*)&g_bnB[1][c4 * 4];
    float4 o;
    o.x = a0.x * xlv.x + b0.x + a1.x * xav.x + b1.x;
    o.y = a0.y * xlv.y + b0.y + a1.y * xav.y + b1.y;
    o.z = a0.z * xlv.z + b0.z + a1.z * xav.z + b1.z;
    o.w = a0.w * xlv.w + b0.w + a1.w * xav.w + b1.w;
    ((float4*)hc)[i] = o;
}

// out = bn2(hc)
__global__ void k_apply(const float* __restrict__ hc, float* __restrict__ out) {
    size_t i = (size_t)blockIdx.x * blockDim.x + threadIdx.x;
    if (i >= (size_t)NN * 32) return;
    int c4 = (int)(i & 31);
    float4 xv = ((const float4*)hc)[i];
    float4 a2 = *(const float4*)&g_bnA[2][c4 * 4];
    float4 b2 = *(const float4*)&g_bnB[2][c4 * 4];
    float4 o;
    o.x = a2.x * xv.x + b2.x;
    o.y = a2.y * xv.y + b2.y;
    o.z = a2.z * xv.z + b2.z;
    o.w = a2.w * xv.w + b2.w;
    ((float4*)out)[i] = o;
}

// ---------------- launcher ----------------
extern "C" void kernel_launch(void* const* d_in, const int* in_sizes, int n_in,
                              void* d_out, int out_size) {
    const float* h      = (const float*)d_in[0];
    const float* eattr  = (const float*)d_in[1];
    const int*   src    = (const int*)d_in[2];
    const int*   dst    = (const int*)d_in[3];
    const float* gin_w1 = (const float*)d_in[4];
    const float* gin_b1 = (const float*)d_in[5];
    const float* gin_w2 = (const float*)d_in[6];
    const float* gin_b2 = (const float*)d_in[7];
    const float* wq = (const float*)d_in[8];
    const float* bq = (const float*)d_in[9];
    const float* wk = (const float*)d_in[10];
    const float* bk = (const float*)d_in[11];
    const float* wv = (const float*)d_in[12];
    const float* bv = (const float*)d_in[13];
    const float* nl_g = (const float*)d_in[14];
    const float* nl_b = (const float*)d_in[15];
    const float* na_g = (const float*)d_in[16];
    const float* na_b = (const float*)d_in[17];
    const float* no_g = (const float*)d_in[18];
    const float* no_b = (const float*)d_in[19];
    const float* ffn1_w = (const float*)d_in[20];
    const float* ffn1_b = (const float*)d_in[21];
    const float* ffn2_w = (const float*)d_in[22];
    const float* ffn2_b = (const float*)d_in[23];

    float* out_hc = (float*)d_out;
    float* out_ea = (float*)d_out + (size_t)NN * HH;

    float *p_buf1, *p_agg, *p_q, *p_k, *p_v, *p_ao, *p_hc, *p_p, *p_den, *p_sum, *p_sumsq;
    cudaGetSymbolAddress((void**)&p_buf1, g_buf1);
    cudaGetSymbolAddress((void**)&p_agg,  g_agg);
    cudaGetSymbolAddress((void**)&p_q,    g_q);
    cudaGetSymbolAddress((void**)&p_k,    g_k);
    cudaGetSymbolAddress((void**)&p_v,    g_v);
    cudaGetSymbolAddress((void**)&p_ao,   g_ao);
    cudaGetSymbolAddress((void**)&p_hc,   g_hc);
    cudaGetSymbolAddress((void**)&p_p,    g_p);
    cudaGetSymbolAddress((void**)&p_den,  g_den);
    cudaGetSymbolAddress((void**)&p_sum,  g_sum);
    cudaGetSymbolAddress((void**)&p_sumsq, g_sumsq);

    const int EB = (EE + 7) / 8;      // edge kernels: 8 warps/block
    const int MB = (NN + 127) / 128;  // gemm row tiles

    // zero scratch that gets atomically accumulated (graph-capturable memsets)
    cudaMemsetAsync(p_agg, 0, (size_t)NN * HH * sizeof(float));
    cudaMemsetAsync(p_ao,  0, (size_t)NN * HH * sizeof(float));
    cudaMemsetAsync(p_den, 0, (size_t)NN * NHH * sizeof(float));
    cudaMemsetAsync(p_sum, 0, 3 * HH * sizeof(float));
    cudaMemsetAsync(p_sumsq, 0, 3 * HH * sizeof(float));

    // --- local branch: GINEConv (also emits the eattr passthrough) ---
    k_edge_agg<<<EB, 256>>>(h, eattr, src, dst, p_agg, out_ea);
    // t1 = relu((h+agg) @ gin_w1^T + gin_b1)
    k_gemm_tc<<<dim3(MB, 1), 256>>>(h, p_agg, gin_w1, gin_b1, nullptr, p_buf1,
                                    NN, HH, HH, 1.f, 1);
    // h_local = t1 @ gin_w2^T + gin_b2   (into g_agg, reuse)
    k_gemm_tc<<<dim3(MB, 1), 256>>>(p_buf1, nullptr, gin_w2, gin_b2, nullptr, p_agg,
                                    NN, HH, HH, 1.f, 0);
    // xl = h + h_local (in-place in g_agg), stats set 0
    k_addstats<<<256, 256>>>(h, p_agg, p_agg, &p_sum[0 * HH], &p_sumsq[0 * HH]);

    // --- global branch: sparse MHA ---
    k_gemm_tc<<<dim3(MB, 1), 256>>>(h, nullptr, wq, bq, nullptr, p_q, NN, HH, HH, 0.25f, 0);
    k_gemm_tc<<<dim3(MB, 1), 256>>>(h, nullptr, wk, bk, nullptr, p_k, NN, HH, HH, 1.f, 0);
    k_gemm_tc<<<dim3(MB, 1), 256>>>(h, nullptr, wv, bv, nullptr, p_v, NN, HH, HH, 1.f, 0);
    k_edge_score<<<EB, 256>>>(p_q, p_k, src, dst, p_p, p_den);
    k_edge_out<<<EB, 256>>>(p_p, p_den, p_v, src, dst, p_ao);
    // xa = h + attn_out (in-place in g_ao), stats set 1
    k_addstats<<<256, 256>>>(h, p_ao, p_ao, &p_sum[1 * HH], &p_sumsq[1 * HH]);

    // finalize BNs 0 and 1, combine
    k_bnfin<<<1, 128>>>(0, nl_g, nl_b);
    k_bnfin<<<1, 128>>>(1, na_g, na_b);
    k_combine<<<(NN * 32 + 255) / 256, 256>>>(p_agg, p_ao, p_hc);

    // --- FFN ---
    // f = relu(hc @ ffn1_w^T + ffn1_b)  [N,256]
    k_gemm_tc<<<dim3(MB, 2), 256>>>(p_hc, nullptr, ffn1_w, ffn1_b, nullptr, p_buf1,
                                    NN, 256, HH, 1.f, 1);
    // hc = hc + f @ ffn2_w^T + ffn2_b  (in-place residual)
    k_gemm_tc<<<dim3(MB, 1), 256>>>(p_buf1, nullptr, ffn2_w, ffn2_b, p_hc, p_hc,
                                    NN, HH, 256, 1.f, 0);
    // stats set 2 (no add, no out)
    k_addstats<<<256, 256>>>(p_hc, nullptr, nullptr, &p_sum[2 * HH], &p_sumsq[2 * HH]);
    k_bnfin<<<1, 128>>>(2, no_g, no_b);
    k_apply<<<(NN * 32 + 255) / 256, 256>>>(p_hc, out_hc);
}

// round 5
// speedup vs baseline: 1.9212x; 1.0823x over previous
#include <cuda_runtime.h>
#include <math.h>

#define NN 50000
#define EE 500000
#define HH 128
#define NHH 8
// DH = 16, scale = 0.25

// ---------------- scratch (device globals; no runtime alloc) ----------------
__device__ float g_buf1[(size_t)NN * 256];  // gin hidden (N,128) then FFN hidden (N,256)
__device__ float g_agg [(size_t)NN * HH];   // edge agg -> xl (in-place)
__device__ float g_q   [(size_t)NN * HH];
__device__ float g_k   [(size_t)NN * HH];
__device__ float g_v   [(size_t)NN * HH];
__device__ float g_ao  [(size_t)NN * HH];   // attn out -> xa (in-place)
__device__ float g_hc  [(size_t)NN * HH];   // combine -> +FFN (in-place)
__device__ float g_p   [(size_t)EE * NHH];  // exp(scores)
__device__ float g_den [(size_t)NN * NHH];
__device__ float g_sum  [3][HH];
__device__ float g_sumsq[3][HH];
__device__ float g_bnA  [3][HH];
__device__ float g_bnB  [3][HH];

// ---------------- small helpers ----------------
__device__ __forceinline__ void red4(float* p, float4 v) {
    asm volatile("red.global.add.v4.f32 [%0], {%1,%2,%3,%4};"
                 :: "l"(p), "f"(v.x), "f"(v.y), "f"(v.z), "f"(v.w) : "memory");
}
__device__ __forceinline__ void redf(float* p, float v) {
    asm volatile("red.global.add.f32 [%0], %1;" :: "l"(p), "f"(v) : "memory");
}
__device__ __forceinline__ unsigned f2tf32(float f) {
    unsigned u;
    asm("cvt.rna.tf32.f32 %0, %1;" : "=r"(u) : "f"(f));
    return u;
}

// ---------------- edge kernels (1 warp per edge, float4 per lane) ----------------
// also writes the eattr passthrough output (fused copy, streaming hints)
__global__ void k_edge_agg(const float* __restrict__ h, const float* __restrict__ ea,
                           const int* __restrict__ src, const int* __restrict__ dst,
                           float* __restrict__ agg, float* __restrict__ ea_out) {
    int e = blockIdx.x * 8 + (threadIdx.x >> 5);
    if (e >= EE) return;
    int lane = threadIdx.x & 31;
    int s = src[e], d = dst[e];
    float4 hv = *(const float4*)(h  + (size_t)s * HH + lane * 4);
    float4 ev = __ldcs((const float4*)(ea + (size_t)e * HH + lane * 4));
    __stcs((float4*)(ea_out + (size_t)e * HH + lane * 4), ev);   // passthrough
    float4 m;
    m.x = fmaxf(hv.x + ev.x, 0.f);
    m.y = fmaxf(hv.y + ev.y, 0.f);
    m.z = fmaxf(hv.z + ev.z, 0.f);
    m.w = fmaxf(hv.w + ev.w, 0.f);
    red4(agg + (size_t)d * HH + lane * 4, m);
}

// per-edge per-head scores; softmax max-subtraction skipped (scores ~O(0.1))
__global__ void k_edge_score(const float* __restrict__ q, const float* __restrict__ k,
                             const int* __restrict__ src, const int* __restrict__ dst,
                             float* __restrict__ p, float* __restrict__ den) {
    int e = blockIdx.x * 8 + (threadIdx.x >> 5);
    if (e >= EE) return;
    int lane = threadIdx.x & 31;
    int s = src[e], d = dst[e];
    float4 qv = *(const float4*)(q + (size_t)s * HH + lane * 4);
    float4 kv = *(const float4*)(k + (size_t)d * HH + lane * 4);
    float part = qv.x * kv.x + qv.y * kv.y + qv.z * kv.z + qv.w * kv.w;
    part += __shfl_xor_sync(0xffffffffu, part, 1);
    part += __shfl_xor_sync(0xffffffffu, part, 2);
    if ((lane & 3) == 0) {
        int hd = lane >> 2;
        float pe = expf(part);
        __stcs(&p[(size_t)e * NHH + hd], pe);
        atomicAdd(&den[(size_t)s * NHH + hd], pe);
    }
}

__global__ void k_edge_out(const float* __restrict__ p, const float* __restrict__ den,
                           const float* __restrict__ v,
                           const int* __restrict__ src, const int* __restrict__ dst,
                           float* __restrict__ ao) {
    int e = blockIdx.x * 8 + (threadIdx.x >> 5);
    if (e >= EE) return;
    int lane = threadIdx.x & 31;
    int s = src[e], d = dst[e];
    int hd = lane >> 2;
    float w = __ldcs(&p[(size_t)e * NHH + hd]) / den[(size_t)s * NHH + hd];
    float4 vv = *(const float4*)(v + (size_t)d * HH + lane * 4);
    float4 m;
    m.x = w * vv.x; m.y = w * vv.y; m.z = w * vv.z; m.w = w * vv.w;
    red4(ao + (size_t)s * HH + lane * 4, m);
}

// ---------------- TF32 tensor-core GEMM ----------------
// C[M,Nc] = act( ((A[+A2]) @ W^T + bias) * scale ) [+res]
// Optional fused BN stats: per-column sum/sumsq of final outputs via
// warp-shuffle column reduction + red.global.add (requires Nc==gridDim.y*128).
__global__ __launch_bounds__(256) void k_gemm_tc(
    const float* __restrict__ A, const float* __restrict__ A2,
    const float* __restrict__ W, const float* __restrict__ bias,
    const float* __restrict__ res, float* __restrict__ C,
    int M, int Nc, int K, float scale, int do_relu,
    float* __restrict__ stat_sum, float* __restrict__ stat_sq)
{
    __shared__ unsigned As[128][36];
    __shared__ unsigned Bs[128][36];
    const int m0 = blockIdx.x * 128;
    const int n0 = blockIdx.y * 128;
    const int tid = threadIdx.x;
    const int wid = tid >> 5;
    const int lane = tid & 31;
    const int g = lane >> 2;       // groupID
    const int t = lane & 3;        // threadID_in_group
    const int wm = wid >> 1;       // 0..3, rows wm*32..
    const int wn = wid & 1;        // 0..1, cols wn*64..

    float acc[2][8][4];
#pragma unroll
    for (int mt = 0; mt < 2; mt++)
#pragma unroll
        for (int nt = 0; nt < 8; nt++)
#pragma unroll
            for (int c = 0; c < 4; c++) acc[mt][nt][c] = 0.f;

    for (int k0 = 0; k0 < K; k0 += 32) {
#pragma unroll
        for (int i = 0; i < 4; i++) {
            int idx = tid + i * 256;          // 0..1023 float4 slots
            int r = idx >> 3;
            int c4 = (idx & 7) * 4;
            int gm = m0 + r;
            float4 va = make_float4(0.f, 0.f, 0.f, 0.f);
            if (gm < M) {
                va = *(const float4*)(A + (size_t)gm * K + k0 + c4);
                if (A2) {
                    float4 v2 = *(const float4*)(A2 + (size_t)gm * K + k0 + c4);
                    va.x += v2.x; va.y += v2.y; va.z += v2.z; va.w += v2.w;
                }
            }
            As[r][c4 + 0] = f2tf32(va.x);
            As[r][c4 + 1] = f2tf32(va.y);
            As[r][c4 + 2] = f2tf32(va.z);
            As[r][c4 + 3] = f2tf32(va.w);
            float4 vb = *(const float4*)(W + (size_t)(n0 + r) * K + k0 + c4);
            Bs[r][c4 + 0] = f2tf32(vb.x);
            Bs[r][c4 + 1] = f2tf32(vb.y);
            Bs[r][c4 + 2] = f2tf32(vb.z);
            Bs[r][c4 + 3] = f2tf32(vb.w);
        }
        __syncthreads();

#pragma unroll
        for (int ks = 0; ks < 4; ks++) {
            const int kb = ks * 8;
            unsigned a[2][4];
#pragma unroll
            for (int mt = 0; mt < 2; mt++) {
                int r = wm * 32 + mt * 16 + g;
                a[mt][0] = As[r][kb + t];
                a[mt][1] = As[r + 8][kb + t];
                a[mt][2] = As[r][kb + t + 4];
                a[mt][3] = As[r + 8][kb + t + 4];
            }
            unsigned b[8][2];
#pragma unroll
            for (int nt = 0; nt < 8; nt++) {
                int r = wn * 64 + nt * 8 + g;
                b[nt][0] = Bs[r][kb + t];
                b[nt][1] = Bs[r][kb + t + 4];
            }
#pragma unroll
            for (int mt = 0; mt < 2; mt++)
#pragma unroll
                for (int nt = 0; nt < 8; nt++) {
                    asm volatile(
                        "mma.sync.aligned.m16n8k8.row.col.f32.tf32.tf32.f32 "
                        "{%0,%1,%2,%3}, {%4,%5,%6,%7}, {%8,%9}, {%0,%1,%2,%3};"
                        : "+f"(acc[mt][nt][0]), "+f"(acc[mt][nt][1]),
                          "+f"(acc[mt][nt][2]), "+f"(acc[mt][nt][3])
                        : "r"(a[mt][0]), "r"(a[mt][1]), "r"(a[mt][2]), "r"(a[mt][3]),
                          "r"(b[nt][0]), "r"(b[nt][1]));
                }
        }
        __syncthreads();
    }

    // epilogue (nt outer so per-column stats stay in 4 registers)
#pragma unroll
    for (int nt = 0; nt < 8; nt++) {
        int gn = n0 + wn * 64 + nt * 8 + 2 * t;
        float b0 = bias[gn], b1 = bias[gn + 1];
        float cs0 = 0.f, cs1 = 0.f, cq0 = 0.f, cq1 = 0.f;
#pragma unroll
        for (int mt = 0; mt < 2; mt++) {
            int row = m0 + wm * 32 + mt * 16 + g;
            if (row < M) {
                float v0 = (acc[mt][nt][0] + b0) * scale;
                float v1 = (acc[mt][nt][1] + b1) * scale;
                if (do_relu) { v0 = fmaxf(v0, 0.f); v1 = fmaxf(v1, 0.f); }
                if (res) {
                    float2 rv = *(const float2*)(res + (size_t)row * Nc + gn);
                    v0 += rv.x; v1 += rv.y;
                }
                *(float2*)(C + (size_t)row * Nc + gn) = make_float2(v0, v1);
                cs0 += v0; cq0 += v0 * v0; cs1 += v1; cq1 += v1 * v1;
            }
            int row2 = row + 8;
            if (row2 < M) {
                float v2 = (acc[mt][nt][2] + b0) * scale;
                float v3 = (acc[mt][nt][3] + b1) * scale;
                if (do_relu) { v2 = fmaxf(v2, 0.f); v3 = fmaxf(v3, 0.f); }
                if (res) {
                    float2 rv = *(const float2*)(res + (size_t)row2 * Nc + gn);
                    v2 += rv.x; v3 += rv.y;
                }
                *(float2*)(C + (size_t)row2 * Nc + gn) = make_float2(v2, v3);
                cs0 += v2; cq0 += v2 * v2; cs1 += v3; cq1 += v3 * v3;
            }
        }
        if (stat_sum) {
#pragma unroll
            for (int off = 4; off <= 16; off <<= 1) {
                cs0 += __shfl_xor_sync(0xffffffffu, cs0, off);
                cs1 += __shfl_xor_sync(0xffffffffu, cs1, off);
                cq0 += __shfl_xor_sync(0xffffffffu, cq0, off);
                cq1 += __shfl_xor_sync(0xffffffffu, cq1, off);
            }
            if (g == 0) {
                redf(&stat_sum[gn], cs0); redf(&stat_sum[gn + 1], cs1);
                redf(&stat_sq[gn],  cq0); redf(&stat_sq[gn + 1],  cq1);
            }
        }
    }
}

// ---------------- xa = h + ao, accumulate stats set (float4, two-level reduce) ----
__global__ __launch_bounds__(256) void k_xa_stats(
    const float* __restrict__ h, const float* __restrict__ ao,
    float* __restrict__ xa, float* __restrict__ sum, float* __restrict__ sumsq)
{
    __shared__ float ss[8][128];
    __shared__ float sq[8][128];
    int tid = threadIdx.x;
    int c = tid & 31;       // float4 column group
    int j = tid >> 5;       // row slot 0..7
    float s[4] = {0.f, 0.f, 0.f, 0.f};
    float q[4] = {0.f, 0.f, 0.f, 0.f};
    for (int r = blockIdx.x * 8 + j; r < NN; r += gridDim.x * 8) {
        size_t idx = (size_t)r * 32 + c;
        float4 hv = ((const float4*)h)[idx];
        float4 av = ((const float4*)ao)[idx];
        float4 v;
        v.x = hv.x + av.x; v.y = hv.y + av.y;
        v.z = hv.z + av.z; v.w = hv.w + av.w;
        ((float4*)xa)[idx] = v;
        s[0] += v.x; q[0] += v.x * v.x;
        s[1] += v.y; q[1] += v.y * v.y;
        s[2] += v.z; q[2] += v.z * v.z;
        s[3] += v.w; q[3] += v.w * v.w;
    }
#pragma unroll
    for (int kk = 0; kk < 4; kk++) { ss[j][c * 4 + kk] = s[kk]; sq[j][c * 4 + kk] = q[kk]; }
    __syncthreads();
    if (tid < 128) {
        float a = 0.f, b = 0.f;
#pragma unroll
        for (int jj = 0; jj < 8; jj++) { a += ss[jj][tid]; b += sq[jj][tid]; }
        redf(&sum[tid], a);
        redf(&sumsq[tid], b);
    }
}

// finalize two BN sets in one launch (256 threads: set = tid>>7)
__global__ void k_bnfin01(const float* __restrict__ g0, const float* __restrict__ b0,
                          const float* __restrict__ g1, const float* __restrict__ b1) {
    int w = threadIdx.x >> 7;
    int c = threadIdx.x & 127;
    const float* g = w ? g1 : g0;
    const float* b = w ? b1 : b0;
    float mean = g_sum[w][c] * (1.f / NN);
    float var  = g_sumsq[w][c] * (1.f / NN) - mean * mean;
    float a = g[c] * rsqrtf(var + 1e-5f);
    g_bnA[w][c] = a;
    g_bnB[w][c] = b[c] - mean * a;
}

__global__ void k_bnfin(int which, const float* __restrict__ g, const float* __restrict__ b) {
    int c = threadIdx.x;
    float mean = g_sum[which][c] * (1.f / NN);
    float var  = g_sumsq[which][c] * (1.f / NN) - mean * mean;
    float a = g[c] * rsqrtf(var + 1e-5f);
    g_bnA[which][c] = a;
    g_bnB[which][c] = b[c] - mean * a;
}

// hc = bn0(xl) + bn1(xa)
__global__ void k_combine(const float* __restrict__ xl, const float* __restrict__ xa,
                          float* __restrict__ hc) {
    size_t i = (size_t)blockIdx.x * blockDim.x + threadIdx.x;
    if (i >= (size_t)NN * 32) return;
    int c4 = (int)(i & 31);
    float4 xlv = ((const float4*)xl)[i];
    float4 xav = ((const float4*)xa)[i];
    float4 a0 = *(const float4*)&g_bnA[0][c4 * 4];
    float4 b0 = *(const float4*)&g_bnB[0][c4 * 4];
    float4 a1 = *(const float4*)&g_bnA[1][c4 * 4];
    float4 b1 = *(const float4*)&g_bnB[1][c4 * 4];
    float4 o;
    o.x = a0.x * xlv.x + b0.x + a1.x * xav.x + b1.x;
    o.y = a0.y * xlv.y + b0.y + a1.y * xav.y + b1.y;
    o.z = a0.z * xlv.z + b0.z + a1.z * xav.z + b1.z;
    o.w = a0.w * xlv.w + b0.w + a1.w * xav.w + b1.w;
    ((float4*)hc)[i] = o;
}

// out = bn2(hc)
__global__ void k_apply(const float* __restrict__ hc, float* __restrict__ out) {
    size_t i = (size_t)blockIdx.x * blockDim.x + threadIdx.x;
    if (i >= (size_t)NN * 32) return;
    int c4 = (int)(i & 31);
    float4 xv = ((const float4*)hc)[i];
    float4 a2 = *(const float4*)&g_bnA[2][c4 * 4];
    float4 b2 = *(const float4*)&g_bnB[2][c4 * 4];
    float4 o;
    o.x = a2.x * xv.x + b2.x;
    o.y = a2.y * xv.y + b2.y;
    o.z = a2.z * xv.z + b2.z;
    o.w = a2.w * xv.w + b2.w;
    ((float4*)out)[i] = o;
}

// ---------------- launcher ----------------
extern "C" void kernel_launch(void* const* d_in, const int* in_sizes, int n_in,
                              void* d_out, int out_size) {
    const float* h      = (const float*)d_in[0];
    const float* eattr  = (const float*)d_in[1];
    const int*   src    = (const int*)d_in[2];
    const int*   dst    = (const int*)d_in[3];
    const float* gin_w1 = (const float*)d_in[4];
    const float* gin_b1 = (const float*)d_in[5];
    const float* gin_w2 = (const float*)d_in[6];
    const float* gin_b2 = (const float*)d_in[7];
    const float* wq = (const float*)d_in[8];
    const float* bq = (const float*)d_in[9];
    const float* wk = (const float*)d_in[10];
    const float* bk = (const float*)d_in[11];
    const float* wv = (const float*)d_in[12];
    const float* bv = (const float*)d_in[13];
    const float* nl_g = (const float*)d_in[14];
    const float* nl_b = (const float*)d_in[15];
    const float* na_g = (const float*)d_in[16];
    const float* na_b = (const float*)d_in[17];
    const float* no_g = (const float*)d_in[18];
    const float* no_b = (const float*)d_in[19];
    const float* ffn1_w = (const float*)d_in[20];
    const float* ffn1_b = (const float*)d_in[21];
    const float* ffn2_w = (const float*)d_in[22];
    const float* ffn2_b = (const float*)d_in[23];

    float* out_hc = (float*)d_out;
    float* out_ea = (float*)d_out + (size_t)NN * HH;

    float *p_buf1, *p_agg, *p_q, *p_k, *p_v, *p_ao, *p_hc, *p_p, *p_den, *p_sum, *p_sumsq;
    cudaGetSymbolAddress((void**)&p_buf1, g_buf1);
    cudaGetSymbolAddress((void**)&p_agg,  g_agg);
    cudaGetSymbolAddress((void**)&p_q,    g_q);
    cudaGetSymbolAddress((void**)&p_k,    g_k);
    cudaGetSymbolAddress((void**)&p_v,    g_v);
    cudaGetSymbolAddress((void**)&p_ao,   g_ao);
    cudaGetSymbolAddress((void**)&p_hc,   g_hc);
    cudaGetSymbolAddress((void**)&p_p,    g_p);
    cudaGetSymbolAddress((void**)&p_den,  g_den);
    cudaGetSymbolAddress((void**)&p_sum,  g_sum);
    cudaGetSymbolAddress((void**)&p_sumsq, g_sumsq);

    // one-time stream/event handles (no device memory involved)
    static cudaStream_t s2 = nullptr;
    static cudaEvent_t ev_fork = nullptr, ev_join = nullptr;
    if (s2 == nullptr) {
        cudaStreamCreateWithFlags(&s2, cudaStreamNonBlocking);
        cudaEventCreateWithFlags(&ev_fork, cudaEventDisableTiming);
        cudaEventCreateWithFlags(&ev_join, cudaEventDisableTiming);
    }

    const int EB = (EE + 7) / 8;      // edge kernels: 8 warps/block
    const int MB = (NN + 127) / 128;  // gemm row tiles

    // zero all atomically-accumulated scratch (before fork)
    cudaMemsetAsync(p_agg, 0, (size_t)NN * HH * sizeof(float));
    cudaMemsetAsync(p_ao,  0, (size_t)NN * HH * sizeof(float));
    cudaMemsetAsync(p_den, 0, (size_t)NN * NHH * sizeof(float));
    cudaMemsetAsync(p_sum, 0, 3 * HH * sizeof(float));
    cudaMemsetAsync(p_sumsq, 0, 3 * HH * sizeof(float));

    // fork: branch B runs on s2 concurrently with branch A on the main stream
    cudaEventRecord(ev_fork, 0);
    cudaStreamWaitEvent(s2, ev_fork, 0);

    // --- branch B (s2): sparse MHA ---
    k_gemm_tc<<<dim3(MB, 1), 256, 0, s2>>>(h, nullptr, wq, bq, nullptr, p_q,
                                           NN, HH, HH, 0.25f, 0, nullptr, nullptr);
    k_gemm_tc<<<dim3(MB, 1), 256, 0, s2>>>(h, nullptr, wk, bk, nullptr, p_k,
                                           NN, HH, HH, 1.f, 0, nullptr, nullptr);
    k_gemm_tc<<<dim3(MB, 1), 256, 0, s2>>>(h, nullptr, wv, bv, nullptr, p_v,
                                           NN, HH, HH, 1.f, 0, nullptr, nullptr);
    k_edge_score<<<EB, 256, 0, s2>>>(p_q, p_k, src, dst, p_p, p_den);
    k_edge_out<<<EB, 256, 0, s2>>>(p_p, p_den, p_v, src, dst, p_ao);
    // xa = h + attn_out (in-place in g_ao), stats set 1
    k_xa_stats<<<512, 256, 0, s2>>>(h, p_ao, p_ao, &p_sum[1 * HH], &p_sumsq[1 * HH]);

    // --- branch A (main stream): GINEConv (also emits the eattr passthrough) ---
    k_edge_agg<<<EB, 256>>>(h, eattr, src, dst, p_agg, out_ea);
    // t1 = relu((h+agg) @ gin_w1^T + gin_b1)
    k_gemm_tc<<<dim3(MB, 1), 256>>>(h, p_agg, gin_w1, gin_b1, nullptr, p_buf1,
                                    NN, HH, HH, 1.f, 1, nullptr, nullptr);
    // xl = h + (t1 @ gin_w2^T + gin_b2), fused stats set 0 (into g_agg)
    k_gemm_tc<<<dim3(MB, 1), 256>>>(p_buf1, nullptr, gin_w2, gin_b2, h, p_agg,
                                    NN, HH, HH, 1.f, 0, &p_sum[0 * HH], &p_sumsq[0 * HH]);

    // join
    cudaEventRecord(ev_join, s2);
    cudaStreamWaitEvent(0, ev_join, 0);

    // finalize BNs 0 and 1, combine
    k_bnfin01<<<1, 256>>>(nl_g, nl_b, na_g, na_b);
    k_combine<<<(NN * 32 + 255) / 256, 256>>>(p_agg, p_ao, p_hc);

    // --- FFN ---
    // f = relu(hc @ ffn1_w^T + ffn1_b)  [N,256]
    k_gemm_tc<<<dim3(MB, 2), 256>>>(p_hc, nullptr, ffn1_w, ffn1_b, nullptr, p_buf1,
                                    NN, 256, HH, 1.f, 1, nullptr, nullptr);
    // hc = hc + f @ ffn2_w^T + ffn2_b  (in-place residual), fused stats set 2
    k_gemm_tc<<<dim3(MB, 1), 256>>>(p_buf1, nullptr, ffn2_w, ffn2_b, p_hc, p_hc,
                                    NN, HH, 256, 1.f, 0, &p_sum[2 * HH], &p_sumsq[2 * HH]);
    k_bnfin<<<1, 128>>>(2, no_g, no_b);
    k_apply<<<(NN * 32 + 255) / 256, 256>>>(p_hc, out_hc);
}

// round 6
// speedup vs baseline: 2.1577x; 1.1231x over previous
#include <cuda_runtime.h>
#include <math.h>

#define NN 50000
#define EE 500000
#define HH 128
#define NHH 8
// DH = 16, scale = 0.25 (folded into q GEMM)

#define MAXDEG_SMEM 64

// ---------------- scratch (device globals; no runtime alloc) ----------------
__device__ float g_buf1[(size_t)NN * 256];  // gin hidden (N,128) then FFN hidden (N,256)
__device__ float g_agg [(size_t)NN * HH];   // z = h+agg -> xl (in-place)
__device__ float g_q   [(size_t)NN * HH];
__device__ float g_k   [(size_t)NN * HH];
__device__ float g_v   [(size_t)NN * HH];
__device__ float g_ao  [(size_t)NN * HH];   // xa
__device__ float g_hc  [(size_t)NN * HH];   // combine -> +FFN (in-place)
__device__ float g_sum  [3][HH];
__device__ float g_sumsq[3][HH];
__device__ float g_bnA  [3][HH];
__device__ float g_bnB  [3][HH];
// CSR scratch
__device__ int  g_cnt_s[NN];
__device__ int  g_cnt_d[NN];
__device__ int  g_fill_s[NN];
__device__ int  g_fill_d[NN];
__device__ int  g_rp_s[NN + 1];
__device__ int  g_rp_d[NN + 1];
__device__ int  g_bsum[2][64];
__device__ int2 g_eps[EE];   // (dst, eid) sorted by src
__device__ int2 g_epd[EE];   // (src, eid) sorted by dst

// ---------------- small helpers ----------------
__device__ __forceinline__ void redf(float* p, float v) {
    asm volatile("red.global.add.f32 [%0], %1;" :: "l"(p), "f"(v) : "memory");
}
__device__ __forceinline__ unsigned f2tf32(float f) {
    unsigned u;
    asm("cvt.rna.tf32.f32 %0, %1;" : "=r"(u) : "f"(f));
    return u;
}

// ---------------- CSR build ----------------
__global__ void k_hist(const int* __restrict__ src, const int* __restrict__ dst,
                       int* __restrict__ cs, int* __restrict__ cd) {
    int e = blockIdx.x * 256 + threadIdx.x;
    if (e >= EE) return;
    atomicAdd(&cs[src[e]], 1);
    atomicAdd(&cd[dst[e]], 1);
}

// exclusive scan over n=NN+1 elements (cnt padded with 0 beyond NN)
__global__ __launch_bounds__(1024) void k_scan_block(const int* __restrict__ cnt,
                                                     int* __restrict__ excl,
                                                     int* __restrict__ bsum) {
    __shared__ int sm[1024];
    int i = blockIdx.x * 1024 + threadIdx.x;
    int v = (i < NN) ? cnt[i] : 0;
    sm[threadIdx.x] = v;
    __syncthreads();
#pragma unroll
    for (int off = 1; off < 1024; off <<= 1) {
        int t = (threadIdx.x >= off) ? sm[threadIdx.x - off] : 0;
        __syncthreads();
        sm[threadIdx.x] += t;
        __syncthreads();
    }
    if (i <= NN) excl[i] = sm[threadIdx.x] - v;
    if (threadIdx.x == 1023) bsum[blockIdx.x] = sm[1023];
}

__global__ void k_scan_tops(int* __restrict__ bsum, int G) {
    if (threadIdx.x == 0) {
        int acc = 0;
        for (int b = 0; b < G; b++) { int t = bsum[b]; bsum[b] = acc; acc += t; }
    }
}

__global__ __launch_bounds__(1024) void k_scan_add(int* __restrict__ excl,
                                                   const int* __restrict__ bsum) {
    int i = blockIdx.x * 1024 + threadIdx.x;
    if (i <= NN) excl[i] += bsum[blockIdx.x];
}

__global__ void k_scatter(const int* __restrict__ src, const int* __restrict__ dst,
                          const int* __restrict__ rps, const int* __restrict__ rpd,
                          int* __restrict__ fills, int* __restrict__ filld,
                          int2* __restrict__ eps, int2* __restrict__ epd) {
    int e = blockIdx.x * 256 + threadIdx.x;
    if (e >= EE) return;
    int s = src[e], d = dst[e];
    int ps = rps[s] + atomicAdd(&fills[s], 1);
    eps[ps] = make_int2(d, e);
    int pd = rpd[d] + atomicAdd(&filld[d], 1);
    epd[pd] = make_int2(s, e);
}

// ---------------- GINE aggregate over dst-CSR (warp per node, no atomics) -------
// z[d] = h[d] + sum_e relu(h[src(e)] + eattr[e]); also emits eattr passthrough.
__global__ __launch_bounds__(256) void k_agg_csr(
    const float* __restrict__ h, const float* __restrict__ ea,
    const int* __restrict__ rpd, const int2* __restrict__ epd,
    float* __restrict__ z, float* __restrict__ ea_out)
{
    int node = blockIdx.x * 8 + (threadIdx.x >> 5);
    if (node >= NN) return;
    int lane = threadIdx.x & 31;
    int j0 = rpd[node], j1 = rpd[node + 1];
    float4 acc = *(const float4*)(h + (size_t)node * HH + lane * 4);
    for (int j = j0; j < j1; j++) {
        int2 pr = __ldg(&epd[j]);
        float4 hv = *(const float4*)(h + (size_t)pr.x * HH + lane * 4);
        float4 ev = __ldcs((const float4*)(ea + (size_t)pr.y * HH + lane * 4));
        __stcs((float4*)(ea_out + (size_t)pr.y * HH + lane * 4), ev);
        acc.x += fmaxf(hv.x + ev.x, 0.f);
        acc.y += fmaxf(hv.y + ev.y, 0.f);
        acc.z += fmaxf(hv.z + ev.z, 0.f);
        acc.w += fmaxf(hv.w + ev.w, 0.f);
    }
    *(float4*)(z + (size_t)node * HH + lane * 4) = acc;
}

// ---------------- fused sparse attention over src-CSR (warp per node) ------------
// Computes softmax over the node's edges, out = sum attn*v[dst], xa = h + out,
// and accumulates BN stat set 1. No global atomics except the tiny stat reds.
__global__ __launch_bounds__(256) void k_attn_csr(
    const float* __restrict__ h, const float* __restrict__ q,
    const float* __restrict__ k, const float* __restrict__ v,
    const int* __restrict__ rps, const int2* __restrict__ eps,
    float* __restrict__ xa, float* __restrict__ sum, float* __restrict__ sumsq)
{
    __shared__ float pbuf[8][MAXDEG_SMEM][NHH];
    __shared__ float ss[HH], sq[HH];
    if (threadIdx.x < HH) { ss[threadIdx.x] = 0.f; sq[threadIdx.x] = 0.f; }
    __syncthreads();
    int wid = threadIdx.x >> 5;
    int lane = threadIdx.x & 31;
    int node = blockIdx.x * 8 + wid;
    if (node < NN) {
        int j0 = rps[node], j1 = rps[node + 1];
        int deg = j1 - j0;
        int hd = lane >> 2, t = lane & 3;
        float4 qv = *(const float4*)(q + (size_t)node * HH + lane * 4);
        float den = 0.f;
        for (int j = 0; j < deg; j++) {
            int2 pr = __ldg(&eps[j0 + j]);
            float4 kv = *(const float4*)(k + (size_t)pr.x * HH + lane * 4);
            float part = qv.x * kv.x + qv.y * kv.y + qv.z * kv.z + qv.w * kv.w;
            part += __shfl_xor_sync(0xffffffffu, part, 1);
            part += __shfl_xor_sync(0xffffffffu, part, 2);
            // all 4 lanes of the head group now hold the score
            float pe = expf(part);
            den += pe;
            if (j < MAXDEG_SMEM && t == 0) pbuf[wid][j][hd] = pe;
        }
        __syncwarp();
        float inv = (deg > 0) ? 1.f / den : 0.f;
        float4 acc = make_float4(0.f, 0.f, 0.f, 0.f);
        for (int j = 0; j < deg; j++) {
            int2 pr = __ldg(&eps[j0 + j]);
            float w;
            if (j < MAXDEG_SMEM) {
                w = pbuf[wid][j][hd] * inv;
            } else {  // rare fallback: recompute
                float4 kv = *(const float4*)(k + (size_t)pr.x * HH + lane * 4);
                float part = qv.x * kv.x + qv.y * kv.y + qv.z * kv.z + qv.w * kv.w;
                part += __shfl_xor_sync(0xffffffffu, part, 1);
                part += __shfl_xor_sync(0xffffffffu, part, 2);
                w = expf(part) * inv;
            }
            float4 vv = *(const float4*)(v + (size_t)pr.x * HH + lane * 4);
            acc.x += w * vv.x; acc.y += w * vv.y;
            acc.z += w * vv.z; acc.w += w * vv.w;
        }
        float4 hv = *(const float4*)(h + (size_t)node * HH + lane * 4);
        float4 o = make_float4(hv.x + acc.x, hv.y + acc.y, hv.z + acc.z, hv.w + acc.w);
        *(float4*)(xa + (size_t)node * HH + lane * 4) = o;
        atomicAdd(&ss[lane * 4 + 0], o.x); atomicAdd(&sq[lane * 4 + 0], o.x * o.x);
        atomicAdd(&ss[lane * 4 + 1], o.y); atomicAdd(&sq[lane * 4 + 1], o.y * o.y);
        atomicAdd(&ss[lane * 4 + 2], o.z); atomicAdd(&sq[lane * 4 + 2], o.z * o.z);
        atomicAdd(&ss[lane * 4 + 3], o.w); atomicAdd(&sq[lane * 4 + 3], o.w * o.w);
    }
    __syncthreads();
    if (threadIdx.x < HH) {
        redf(&sum[threadIdx.x], ss[threadIdx.x]);
        redf(&sumsq[threadIdx.x], sq[threadIdx.x]);
    }
}

// ---------------- TF32 tensor-core GEMM ----------------
// C[M,Nc] = act( ((A) @ W^T + bias) * scale ) [+res], optional fused column stats.
__global__ __launch_bounds__(256) void k_gemm_tc(
    const float* __restrict__ A,
    const float* __restrict__ W, const float* __restrict__ bias,
    const float* __restrict__ res, float* __restrict__ C,
    int M, int Nc, int K, float scale, int do_relu,
    float* __restrict__ stat_sum, float* __restrict__ stat_sq)
{
    __shared__ unsigned As[128][36];
    __shared__ unsigned Bs[128][36];
    const int m0 = blockIdx.x * 128;
    const int n0 = blockIdx.y * 128;
    const int tid = threadIdx.x;
    const int wid = tid >> 5;
    const int lane = tid & 31;
    const int g = lane >> 2;
    const int t = lane & 3;
    const int wm = wid >> 1;
    const int wn = wid & 1;

    float acc[2][8][4];
#pragma unroll
    for (int mt = 0; mt < 2; mt++)
#pragma unroll
        for (int nt = 0; nt < 8; nt++)
#pragma unroll
            for (int c = 0; c < 4; c++) acc[mt][nt][c] = 0.f;

    for (int k0 = 0; k0 < K; k0 += 32) {
#pragma unroll
        for (int i = 0; i < 4; i++) {
            int idx = tid + i * 256;
            int r = idx >> 3;
            int c4 = (idx & 7) * 4;
            int gm = m0 + r;
            float4 va = make_float4(0.f, 0.f, 0.f, 0.f);
            if (gm < M) va = *(const float4*)(A + (size_t)gm * K + k0 + c4);
            As[r][c4 + 0] = f2tf32(va.x);
            As[r][c4 + 1] = f2tf32(va.y);
            As[r][c4 + 2] = f2tf32(va.z);
            As[r][c4 + 3] = f2tf32(va.w);
            float4 vb = *(const float4*)(W + (size_t)(n0 + r) * K + k0 + c4);
            Bs[r][c4 + 0] = f2tf32(vb.x);
            Bs[r][c4 + 1] = f2tf32(vb.y);
            Bs[r][c4 + 2] = f2tf32(vb.z);
            Bs[r][c4 + 3] = f2tf32(vb.w);
        }
        __syncthreads();

#pragma unroll
        for (int ks = 0; ks < 4; ks++) {
            const int kb = ks * 8;
            unsigned a[2][4];
#pragma unroll
            for (int mt = 0; mt < 2; mt++) {
                int r = wm * 32 + mt * 16 + g;
                a[mt][0] = As[r][kb + t];
                a[mt][1] = As[r + 8][kb + t];
                a[mt][2] = As[r][kb + t + 4];
                a[mt][3] = As[r + 8][kb + t + 4];
            }
            unsigned b[8][2];
#pragma unroll
            for (int nt = 0; nt < 8; nt++) {
                int r = wn * 64 + nt * 8 + g;
                b[nt][0] = Bs[r][kb + t];
                b[nt][1] = Bs[r][kb + t + 4];
            }
#pragma unroll
            for (int mt = 0; mt < 2; mt++)
#pragma unroll
                for (int nt = 0; nt < 8; nt++) {
                    asm volatile(
                        "mma.sync.aligned.m16n8k8.row.col.f32.tf32.tf32.f32 "
                        "{%0,%1,%2,%3}, {%4,%5,%6,%7}, {%8,%9}, {%0,%1,%2,%3};"
                        : "+f"(acc[mt][nt][0]), "+f"(acc[mt][nt][1]),
                          "+f"(acc[mt][nt][2]), "+f"(acc[mt][nt][3])
                        : "r"(a[mt][0]), "r"(a[mt][1]), "r"(a[mt][2]), "r"(a[mt][3]),
                          "r"(b[nt][0]), "r"(b[nt][1]));
                }
        }
        __syncthreads();
    }

#pragma unroll
    for (int nt = 0; nt < 8; nt++) {
        int gn = n0 + wn * 64 + nt * 8 + 2 * t;
        float b0 = bias[gn], b1 = bias[gn + 1];
        float cs0 = 0.f, cs1 = 0.f, cq0 = 0.f, cq1 = 0.f;
#pragma unroll
        for (int mt = 0; mt < 2; mt++) {
            int row = m0 + wm * 32 + mt * 16 + g;
            if (row < M) {
                float v0 = (acc[mt][nt][0] + b0) * scale;
                float v1 = (acc[mt][nt][1] + b1) * scale;
                if (do_relu) { v0 = fmaxf(v0, 0.f); v1 = fmaxf(v1, 0.f); }
                if (res) {
                    float2 rv = *(const float2*)(res + (size_t)row * Nc + gn);
                    v0 += rv.x; v1 += rv.y;
                }
                *(float2*)(C + (size_t)row * Nc + gn) = make_float2(v0, v1);
                cs0 += v0; cq0 += v0 * v0; cs1 += v1; cq1 += v1 * v1;
            }
            int row2 = row + 8;
            if (row2 < M) {
                float v2 = (acc[mt][nt][2] + b0) * scale;
                float v3 = (acc[mt][nt][3] + b1) * scale;
                if (do_relu) { v2 = fmaxf(v2, 0.f); v3 = fmaxf(v3, 0.f); }
                if (res) {
                    float2 rv = *(const float2*)(res + (size_t)row2 * Nc + gn);
                    v2 += rv.x; v3 += rv.y;
                }
                *(float2*)(C + (size_t)row2 * Nc + gn) = make_float2(v2, v3);
                cs0 += v2; cq0 += v2 * v2; cs1 += v3; cq1 += v3 * v3;
            }
        }
        if (stat_sum) {
#pragma unroll
            for (int off = 4; off <= 16; off <<= 1) {
                cs0 += __shfl_xor_sync(0xffffffffu, cs0, off);
                cs1 += __shfl_xor_sync(0xffffffffu, cs1, off);
                cq0 += __shfl_xor_sync(0xffffffffu, cq0, off);
                cq1 += __shfl_xor_sync(0xffffffffu, cq1, off);
            }
            if (g == 0) {
                redf(&stat_sum[gn], cs0); redf(&stat_sum[gn + 1], cs1);
                redf(&stat_sq[gn],  cq0); redf(&stat_sq[gn + 1],  cq1);
            }
        }
    }
}

// ---------------- BN finalize + apply ----------------
__global__ void k_bnfin01(const float* __restrict__ g0, const float* __restrict__ b0,
                          const float* __restrict__ g1, const float* __restrict__ b1) {
    int w = threadIdx.x >> 7;
    int c = threadIdx.x & 127;
    const float* g = w ? g1 : g0;
    const float* b = w ? b1 : b0;
    float mean = g_sum[w][c] * (1.f / NN);
    float var  = g_sumsq[w][c] * (1.f / NN) - mean * mean;
    float a = g[c] * rsqrtf(var + 1e-5f);
    g_bnA[w][c] = a;
    g_bnB[w][c] = b[c] - mean * a;
}

__global__ void k_bnfin(int which, const float* __restrict__ g, const float* __restrict__ b) {
    int c = threadIdx.x;
    float mean = g_sum[which][c] * (1.f / NN);
    float var  = g_sumsq[which][c] * (1.f / NN) - mean * mean;
    float a = g[c] * rsqrtf(var + 1e-5f);
    g_bnA[which][c] = a;
    g_bnB[which][c] = b[c] - mean * a;
}

__global__ void k_combine(const float* __restrict__ xl, const float* __restrict__ xa,
                          float* __restrict__ hc) {
    size_t i = (size_t)blockIdx.x * blockDim.x + threadIdx.x;
    if (i >= (size_t)NN * 32) return;
    int c4 = (int)(i & 31);
    float4 xlv = ((const float4*)xl)[i];
    float4 xav = ((const float4*)xa)[i];
    float4 a0 = *(const float4*)&g_bnA[0][c4 * 4];
    float4 b0 = *(const float4*)&g_bnB[0][c4 * 4];
    float4 a1 = *(const float4*)&g_bnA[1][c4 * 4];
    float4 b1 = *(const float4*)&g_bnB[1][c4 * 4];
    float4 o;
    o.x = a0.x * xlv.x + b0.x + a1.x * xav.x + b1.x;
    o.y = a0.y * xlv.y + b0.y + a1.y * xav.y + b1.y;
    o.z = a0.z * xlv.z + b0.z + a1.z * xav.z + b1.z;
    o.w = a0.w * xlv.w + b0.w + a1.w * xav.w + b1.w;
    ((float4*)hc)[i] = o;
}

__global__ void k_apply(const float* __restrict__ hc, float* __restrict__ out) {
    size_t i = (size_t)blockIdx.x * blockDim.x + threadIdx.x;
    if (i >= (size_t)NN * 32) return;
    int c4 = (int)(i & 31);
    float4 xv = ((const float4*)hc)[i];
    float4 a2 = *(const float4*)&g_bnA[2][c4 * 4];
    float4 b2 = *(const float4*)&g_bnB[2][c4 * 4];
    float4 o;
    o.x = a2.x * xv.x + b2.x;
    o.y = a2.y * xv.y + b2.y;
    o.z = a2.z * xv.z + b2.z;
    o.w = a2.w * xv.w + b2.w;
    ((float4*)out)[i] = o;
}

// ---------------- launcher ----------------
extern "C" void kernel_launch(void* const* d_in, const int* in_sizes, int n_in,
                              void* d_out, int out_size) {
    const float* h      = (const float*)d_in[0];
    const float* eattr  = (const float*)d_in[1];
    const int*   src    = (const int*)d_in[2];
    const int*   dst    = (const int*)d_in[3];
    const float* gin_w1 = (const float*)d_in[4];
    const float* gin_b1 = (const float*)d_in[5];
    const float* gin_w2 = (const float*)d_in[6];
    const float* gin_b2 = (const float*)d_in[7];
    const float* wq = (const float*)d_in[8];
    const float* bq = (const float*)d_in[9];
    const float* wk = (const float*)d_in[10];
    const float* bk = (const float*)d_in[11];
    const float* wv = (const float*)d_in[12];
    const float* bv = (const float*)d_in[13];
    const float* nl_g = (const float*)d_in[14];
    const float* nl_b = (const float*)d_in[15];
    const float* na_g = (const float*)d_in[16];
    const float* na_b = (const float*)d_in[17];
    const float* no_g = (const float*)d_in[18];
    const float* no_b = (const float*)d_in[19];
    const float* ffn1_w = (const float*)d_in[20];
    const float* ffn1_b = (const float*)d_in[21];
    const float* ffn2_w = (const float*)d_in[22];
    const float* ffn2_b = (const float*)d_in[23];

    float* out_hc = (float*)d_out;
    float* out_ea = (float*)d_out + (size_t)NN * HH;

    float *p_buf1, *p_agg, *p_q, *p_k, *p_v, *p_ao, *p_hc, *p_sum, *p_sumsq;
    int *p_cnt_s, *p_cnt_d, *p_fill_s, *p_fill_d, *p_rp_s, *p_rp_d, *p_bsum;
    int2 *p_eps, *p_epd;
    cudaGetSymbolAddress((void**)&p_buf1, g_buf1);
    cudaGetSymbolAddress((void**)&p_agg,  g_agg);
    cudaGetSymbolAddress((void**)&p_q,    g_q);
    cudaGetSymbolAddress((void**)&p_k,    g_k);
    cudaGetSymbolAddress((void**)&p_v,    g_v);
    cudaGetSymbolAddress((void**)&p_ao,   g_ao);
    cudaGetSymbolAddress((void**)&p_hc,   g_hc);
    cudaGetSymbolAddress((void**)&p_sum,  g_sum);
    cudaGetSymbolAddress((void**)&p_sumsq, g_sumsq);
    cudaGetSymbolAddress((void**)&p_cnt_s, g_cnt_s);
    cudaGetSymbolAddress((void**)&p_cnt_d, g_cnt_d);
    cudaGetSymbolAddress((void**)&p_fill_s, g_fill_s);
    cudaGetSymbolAddress((void**)&p_fill_d, g_fill_d);
    cudaGetSymbolAddress((void**)&p_rp_s, g_rp_s);
    cudaGetSymbolAddress((void**)&p_rp_d, g_rp_d);
    cudaGetSymbolAddress((void**)&p_bsum, g_bsum);
    cudaGetSymbolAddress((void**)&p_eps, g_eps);
    cudaGetSymbolAddress((void**)&p_epd, g_epd);

    static cudaStream_t s2 = nullptr;
    static cudaEvent_t ev_fork = nullptr, ev_csr = nullptr, ev_join = nullptr;
    if (s2 == nullptr) {
        cudaStreamCreateWithFlags(&s2, cudaStreamNonBlocking);
        cudaEventCreateWithFlags(&ev_fork, cudaEventDisableTiming);
        cudaEventCreateWithFlags(&ev_csr,  cudaEventDisableTiming);
        cudaEventCreateWithFlags(&ev_join, cudaEventDisableTiming);
    }

    const int EB = (EE + 255) / 256;        // edge-parallel blocks
    const int NB = (NN + 7) / 8;            // warp-per-node blocks
    const int MB = (NN + 127) / 128;        // gemm row tiles
    const int SG = (NN + 1024) / 1024;      // scan blocks (covers NN+1)

    // zero the small accumulated scratch
    cudaMemsetAsync(p_cnt_s, 0, NN * sizeof(int));
    cudaMemsetAsync(p_cnt_d, 0, NN * sizeof(int));
    cudaMemsetAsync(p_fill_s, 0, NN * sizeof(int));
    cudaMemsetAsync(p_fill_d, 0, NN * sizeof(int));
    cudaMemsetAsync(p_sum, 0, 3 * HH * sizeof(float));
    cudaMemsetAsync(p_sumsq, 0, 3 * HH * sizeof(float));

    // fork: QKV GEMMs need only h — start immediately on s2 while main builds CSR
    cudaEventRecord(ev_fork, 0);
    cudaStreamWaitEvent(s2, ev_fork, 0);
    k_gemm_tc<<<dim3(MB, 1), 256, 0, s2>>>(h, wq, bq, nullptr, p_q,
                                           NN, HH, HH, 0.25f, 0, nullptr, nullptr);
    k_gemm_tc<<<dim3(MB, 1), 256, 0, s2>>>(h, wk, bk, nullptr, p_k,
                                           NN, HH, HH, 1.f, 0, nullptr, nullptr);
    k_gemm_tc<<<dim3(MB, 1), 256, 0, s2>>>(h, wv, bv, nullptr, p_v,
                                           NN, HH, HH, 1.f, 0, nullptr, nullptr);

    // main: CSR build (both directions)
    k_hist<<<EB, 256>>>(src, dst, p_cnt_s, p_cnt_d);
    k_scan_block<<<SG, 1024>>>(p_cnt_s, p_rp_s, &p_bsum[0]);
    k_scan_block<<<SG, 1024>>>(p_cnt_d, p_rp_d, &p_bsum[64]);
    k_scan_tops<<<1, 32>>>(&p_bsum[0], SG);
    k_scan_tops<<<1, 32>>>(&p_bsum[64], SG);
    k_scan_add<<<SG, 1024>>>(p_rp_s, &p_bsum[0]);
    k_scan_add<<<SG, 1024>>>(p_rp_d, &p_bsum[64]);
    k_scatter<<<EB, 256>>>(src, dst, p_rp_s, p_rp_d, p_fill_s, p_fill_d, p_eps, p_epd);
    cudaEventRecord(ev_csr, 0);

    // s2: fused attention (after QKV + CSR)
    cudaStreamWaitEvent(s2, ev_csr, 0);
    k_attn_csr<<<NB, 256, 0, s2>>>(h, p_q, p_k, p_v, p_rp_s, p_eps,
                                   p_ao, &p_sum[1 * HH], &p_sumsq[1 * HH]);
    cudaEventRecord(ev_join, s2);

    // main: GINE aggregate + GIN MLP (stats set 0 fused in second GEMM)
    k_agg_csr<<<NB, 256>>>(h, eattr, p_rp_d, p_epd, p_agg, out_ea);
    k_gemm_tc<<<dim3(MB, 1), 256>>>(p_agg, gin_w1, gin_b1, nullptr, p_buf1,
                                    NN, HH, HH, 1.f, 1, nullptr, nullptr);
    k_gemm_tc<<<dim3(MB, 1), 256>>>(p_buf1, gin_w2, gin_b2, h, p_agg,
                                    NN, HH, HH, 1.f, 0, &p_sum[0 * HH], &p_sumsq[0 * HH]);

    // join
    cudaStreamWaitEvent(0, ev_join, 0);

    // finalize BNs 0/1, combine, FFN, BN2, output
    k_bnfin01<<<1, 256>>>(nl_g, nl_b, na_g, na_b);
    k_combine<<<(NN * 32 + 255) / 256, 256>>>(p_agg, p_ao, p_hc);
    k_gemm_tc<<<dim3(MB, 2), 256>>>(p_hc, ffn1_w, ffn1_b, nullptr, p_buf1,
                                    NN, 256, HH, 1.f, 1, nullptr, nullptr);
    k_gemm_tc<<<dim3(MB, 1), 256>>>(p_buf1, ffn2_w, ffn2_b, p_hc, p_hc,
                                    NN, HH, 256, 1.f, 0, &p_sum[2 * HH], &p_sumsq[2 * HH]);
    k_bnfin<<<1, 128>>>(2, no_g, no_b);
    k_apply<<<(NN * 32 + 255) / 256, 256>>>(p_hc, out_hc);
}

// round 8
// speedup vs baseline: 2.3065x; 1.0690x over previous
#include <cuda_runtime.h>
#include <cuda_fp16.h>
#include <math.h>

#define NN 50000
#define EE 500000
#define HH 128
#define NHH 8
// DH = 16, scale = 0.25 (folded into q GEMM)

#define MAXDEG_SMEM 64

// ---------------- scratch (device globals; no runtime alloc) ----------------
__device__ float g_buf1[(size_t)NN * 256];  // gin hidden (N,128) then FFN hidden (N,256)
__device__ float g_agg [(size_t)NN * HH];   // z = h+agg -> xl (in-place)
__device__ float g_q   [(size_t)NN * HH];
__device__ float g_k   [(size_t)NN * HH];
__device__ float g_v   [(size_t)NN * HH];
__device__ float g_ao  [(size_t)NN * HH];   // xa
__device__ float g_hc  [(size_t)NN * HH];   // combine -> +FFN (in-place)
__device__ float g_sum  [3][HH];
__device__ float g_sumsq[3][HH];
__device__ float g_bnA  [3][HH];
__device__ float g_bnB  [3][HH];
// CSR scratch
__device__ int  g_cnt_s[NN];
__device__ int  g_cnt_d[NN];
__device__ int  g_fill_s[NN];
__device__ int  g_fill_d[NN];
__device__ int  g_rp_s[NN + 1];
__device__ int  g_rp_d[NN + 1];
__device__ int  g_bsum[2][64];
__device__ int2 g_eps[EE];   // (dst, eid) sorted by src
__device__ int2 g_epd[EE];   // (src, eid) sorted by dst

// ---------------- small helpers ----------------
__device__ __forceinline__ void redf(float* p, float v) {
    asm volatile("red.global.add.f32 [%0], %1;" :: "l"(p), "f"(v) : "memory");
}

// ---------------- CSR build ----------------
__global__ void k_hist(const int* __restrict__ src, const int* __restrict__ dst,
                       int* __restrict__ cs, int* __restrict__ cd) {
    int e = blockIdx.x * 256 + threadIdx.x;
    if (e >= EE) return;
    atomicAdd(&cs[src[e]], 1);
    atomicAdd(&cd[dst[e]], 1);
}

__global__ __launch_bounds__(1024) void k_scan_block(const int* __restrict__ cnt,
                                                     int* __restrict__ excl,
                                                     int* __restrict__ bsum) {
    __shared__ int sm[1024];
    int i = blockIdx.x * 1024 + threadIdx.x;
    int v = (i < NN) ? cnt[i] : 0;
    sm[threadIdx.x] = v;
    __syncthreads();
#pragma unroll
    for (int off = 1; off < 1024; off <<= 1) {
        int t = (threadIdx.x >= off) ? sm[threadIdx.x - off] : 0;
        __syncthreads();
        sm[threadIdx.x] += t;
        __syncthreads();
    }
    if (i <= NN) excl[i] = sm[threadIdx.x] - v;
    if (threadIdx.x == 1023) bsum[blockIdx.x] = sm[1023];
}

__global__ void k_scan_tops(int* __restrict__ bsum, int G) {
    if (threadIdx.x == 0) {
        int acc = 0;
        for (int b = 0; b < G; b++) { int t = bsum[b]; bsum[b] = acc; acc += t; }
    }
}

__global__ __launch_bounds__(1024) void k_scan_add(int* __restrict__ excl,
                                                   const int* __restrict__ bsum) {
    int i = blockIdx.x * 1024 + threadIdx.x;
    if (i <= NN) excl[i] += bsum[blockIdx.x];
}

__global__ void k_scatter(const int* __restrict__ src, const int* __restrict__ dst,
                          const int* __restrict__ rps, const int* __restrict__ rpd,
                          int* __restrict__ fills, int* __restrict__ filld,
                          int2* __restrict__ eps, int2* __restrict__ epd) {
    int e = blockIdx.x * 256 + threadIdx.x;
    if (e >= EE) return;
    int s = src[e], d = dst[e];
    int ps = rps[s] + atomicAdd(&fills[s], 1);
    eps[ps] = make_int2(d, e);
    int pd = rpd[d] + atomicAdd(&filld[d], 1);
    epd[pd] = make_int2(s, e);
}

// ---------------- GINE aggregate over dst-CSR (warp per node, no atomics) -------
__global__ __launch_bounds__(256) void k_agg_csr(
    const float* __restrict__ h, const float* __restrict__ ea,
    const int* __restrict__ rpd, const int2* __restrict__ epd,
    float* __restrict__ z, float* __restrict__ ea_out)
{
    int node = blockIdx.x * 8 + (threadIdx.x >> 5);
    if (node >= NN) return;
    int lane = threadIdx.x & 31;
    int j0 = rpd[node], j1 = rpd[node + 1];
    float4 acc = *(const float4*)(h + (size_t)node * HH + lane * 4);
    for (int j = j0; j < j1; j++) {
        int2 pr = __ldg(&epd[j]);
        float4 hv = *(const float4*)(h + (size_t)pr.x * HH + lane * 4);
        float4 ev = __ldcs((const float4*)(ea + (size_t)pr.y * HH + lane * 4));
        __stcs((float4*)(ea_out + (size_t)pr.y * HH + lane * 4), ev);
        acc.x += fmaxf(hv.x + ev.x, 0.f);
        acc.y += fmaxf(hv.y + ev.y, 0.f);
        acc.z += fmaxf(hv.z + ev.z, 0.f);
        acc.w += fmaxf(hv.w + ev.w, 0.f);
    }
    *(float4*)(z + (size_t)node * HH + lane * 4) = acc;
}

// ---------------- fused sparse attention over src-CSR (warp per node) ------------
__global__ __launch_bounds__(256) void k_attn_csr(
    const float* __restrict__ h, const float* __restrict__ q,
    const float* __restrict__ k, const float* __restrict__ v,
    const int* __restrict__ rps, const int2* __restrict__ eps,
    float* __restrict__ xa, float* __restrict__ sum, float* __restrict__ sumsq)
{
    __shared__ float pbuf[8][MAXDEG_SMEM][NHH];
    __shared__ float ss[HH], sq[HH];
    if (threadIdx.x < HH) { ss[threadIdx.x] = 0.f; sq[threadIdx.x] = 0.f; }
    __syncthreads();
    int wid = threadIdx.x >> 5;
    int lane = threadIdx.x & 31;
    int node = blockIdx.x * 8 + wid;
    if (node < NN) {
        int j0 = rps[node], j1 = rps[node + 1];
        int deg = j1 - j0;
        int hd = lane >> 2, t = lane & 3;
        float4 qv = *(const float4*)(q + (size_t)node * HH + lane * 4);
        float den = 0.f;
        for (int j = 0; j < deg; j++) {
            int2 pr = __ldg(&eps[j0 + j]);
            float4 kv = *(const float4*)(k + (size_t)pr.x * HH + lane * 4);
            float part = qv.x * kv.x + qv.y * kv.y + qv.z * kv.z + qv.w * kv.w;
            part += __shfl_xor_sync(0xffffffffu, part, 1);
            part += __shfl_xor_sync(0xffffffffu, part, 2);
            float pe = expf(part);
            den += pe;
            if (j < MAXDEG_SMEM && t == 0) pbuf[wid][j][hd] = pe;
        }
        __syncwarp();
        float inv = (deg > 0) ? 1.f / den : 0.f;
        float4 acc = make_float4(0.f, 0.f, 0.f, 0.f);
        for (int j = 0; j < deg; j++) {
            int2 pr = __ldg(&eps[j0 + j]);
            float w;
            if (j < MAXDEG_SMEM) {
                w = pbuf[wid][j][hd] * inv;
            } else {
                float4 kv = *(const float4*)(k + (size_t)pr.x * HH + lane * 4);
                float part = qv.x * kv.x + qv.y * kv.y + qv.z * kv.z + qv.w * kv.w;
                part += __shfl_xor_sync(0xffffffffu, part, 1);
                part += __shfl_xor_sync(0xffffffffu, part, 2);
                w = expf(part) * inv;
            }
            float4 vv = *(const float4*)(v + (size_t)pr.x * HH + lane * 4);
            acc.x += w * vv.x; acc.y += w * vv.y;
            acc.z += w * vv.z; acc.w += w * vv.w;
        }
        float4 hv = *(const float4*)(h + (size_t)node * HH + lane * 4);
        float4 o = make_float4(hv.x + acc.x, hv.y + acc.y, hv.z + acc.z, hv.w + acc.w);
        *(float4*)(xa + (size_t)node * HH + lane * 4) = o;
        atomicAdd(&ss[lane * 4 + 0], o.x); atomicAdd(&sq[lane * 4 + 0], o.x * o.x);
        atomicAdd(&ss[lane * 4 + 1], o.y); atomicAdd(&sq[lane * 4 + 1], o.y * o.y);
        atomicAdd(&ss[lane * 4 + 2], o.z); atomicAdd(&sq[lane * 4 + 2], o.z * o.z);
        atomicAdd(&ss[lane * 4 + 3], o.w); atomicAdd(&sq[lane * 4 + 3], o.w * o.w);
    }
    __syncthreads();
    if (threadIdx.x < HH) {
        redf(&sum[threadIdx.x], ss[threadIdx.x]);
        redf(&sumsq[threadIdx.x], sq[threadIdx.x]);
    }
}

// ---------------- FP16 tensor-core GEMM (fp32 accumulate) ----------------
// C[M,Nc] = act( ((A) @ W^T + bias) * scale ) [+res], optional fused column stats.
// Block tile 128x128, K chunked by 32 (2 x k16 mma steps). smem stride 20 half2
// (80B) -> conflict-free fragment loads (g*20+t covers 8 disjoint 4-lane groups).
__global__ __launch_bounds__(256) void k_gemm_tc(
    const float* __restrict__ A,
    const float* __restrict__ W, const float* __restrict__ bias,
    const float* __restrict__ res, float* __restrict__ C,
    int M, int Nc, int K, float scale, int do_relu,
    float* __restrict__ stat_sum, float* __restrict__ stat_sq)
{
    __shared__ __half2 As[128][20];
    __shared__ __half2 Bs[128][20];
    const int m0 = blockIdx.x * 128;
    const int n0 = blockIdx.y * 128;
    const int tid = threadIdx.x;
    const int wid = tid >> 5;
    const int lane = tid & 31;
    const int g = lane >> 2;
    const int t = lane & 3;
    const int wm = wid >> 1;
    const int wn = wid & 1;

    float acc[2][8][4];
#pragma unroll
    for (int mt = 0; mt < 2; mt++)
#pragma unroll
        for (int nt = 0; nt < 8; nt++)
#pragma unroll
            for (int c = 0; c < 4; c++) acc[mt][nt][c] = 0.f;

    for (int k0 = 0; k0 < K; k0 += 32) {
#pragma unroll
        for (int i = 0; i < 4; i++) {
            int idx = tid + i * 256;          // 0..1023 float4 slots
            int r = idx >> 3;
            int c4 = (idx & 7) * 4;           // float col in chunk
            int ch = c4 >> 1;                 // half2 col
            int gm = m0 + r;
            float4 va = make_float4(0.f, 0.f, 0.f, 0.f);
            if (gm < M) va = *(const float4*)(A + (size_t)gm * K + k0 + c4);
            As[r][ch + 0] = __floats2half2_rn(va.x, va.y);
            As[r][ch + 1] = __floats2half2_rn(va.z, va.w);
            float4 vb = *(const float4*)(W + (size_t)(n0 + r) * K + k0 + c4);
            Bs[r][ch + 0] = __floats2half2_rn(vb.x, vb.y);
            Bs[r][ch + 1] = __floats2half2_rn(vb.z, vb.w);
        }
        __syncthreads();

#pragma unroll
        for (int ks = 0; ks < 2; ks++) {
            const int kb = ks * 8;            // half2 offset (16 k values)
            unsigned a[2][4];
#pragma unroll
            for (int mt = 0; mt < 2; mt++) {
                int r = wm * 32 + mt * 16 + g;
                a[mt][0] = *(const unsigned*)&As[r][kb + t];
                a[mt][1] = *(const unsigned*)&As[r + 8][kb + t];
                a[mt][2] = *(const unsigned*)&As[r][kb + t + 4];
                a[mt][3] = *(const unsigned*)&As[r + 8][kb + t + 4];
            }
            unsigned b[8][2];
#pragma unroll
            for (int nt = 0; nt < 8; nt++) {
                int r = wn * 64 + nt * 8 + g;
                b[nt][0] = *(const unsigned*)&Bs[r][kb + t];
                b[nt][1] = *(const unsigned*)&Bs[r][kb + t + 4];
            }
#pragma unroll
            for (int mt = 0; mt < 2; mt++)
#pragma unroll
                for (int nt = 0; nt < 8; nt++) {
                    asm volatile(
                        "mma.sync.aligned.m16n8k16.row.col.f32.f16.f16.f32 "
                        "{%0,%1,%2,%3}, {%4,%5,%6,%7}, {%8,%9}, {%0,%1,%2,%3};"
                        : "+f"(acc[mt][nt][0]), "+f"(acc[mt][nt][1]),
                          "+f"(acc[mt][nt][2]), "+f"(acc[mt][nt][3])
                        : "r"(a[mt][0]), "r"(a[mt][1]), "r"(a[mt][2]), "r"(a[mt][3]),
                          "r"(b[nt][0]), "r"(b[nt][1]));
                }
        }
        __syncthreads();
    }

#pragma unroll
    for (int nt = 0; nt < 8; nt++) {
        int gn = n0 + wn * 64 + nt * 8 + 2 * t;
        float b0 = bias[gn], b1 = bias[gn + 1];
        float cs0 = 0.f, cs1 = 0.f, cq0 = 0.f, cq1 = 0.f;
#pragma unroll
        for (int mt = 0; mt < 2; mt++) {
            int row = m0 + wm * 32 + mt * 16 + g;
            if (row < M) {
                float v0 = (acc[mt][nt][0] + b0) * scale;
                float v1 = (acc[mt][nt][1] + b1) * scale;
                if (do_relu) { v0 = fmaxf(v0, 0.f); v1 = fmaxf(v1, 0.f); }
                if (res) {
                    float2 rv = *(const float2*)(res + (size_t)row * Nc + gn);
                    v0 += rv.x; v1 += rv.y;
                }
                *(float2*)(C + (size_t)row * Nc + gn) = make_float2(v0, v1);
                cs0 += v0; cq0 += v0 * v0; cs1 += v1; cq1 += v1 * v1;
            }
            int row2 = row + 8;
            if (row2 < M) {
                float v2 = (acc[mt][nt][2] + b0) * scale;
                float v3 = (acc[mt][nt][3] + b1) * scale;
                if (do_relu) { v2 = fmaxf(v2, 0.f); v3 = fmaxf(v3, 0.f); }
                if (res) {
                    float2 rv = *(const float2*)(res + (size_t)row2 * Nc + gn);
                    v2 += rv.x; v3 += rv.y;
                }
                *(float2*)(C + (size_t)row2 * Nc + gn) = make_float2(v2, v3);
                cs0 += v2; cq0 += v2 * v2; cs1 += v3; cq1 += v3 * v3;
            }
        }
        if (stat_sum) {
#pragma unroll
            for (int off = 4; off <= 16; off <<= 1) {
                cs0 += __shfl_xor_sync(0xffffffffu, cs0, off);
                cs1 += __shfl_xor_sync(0xffffffffu, cs1, off);
                cq0 += __shfl_xor_sync(0xffffffffu, cq0, off);
                cq1 += __shfl_xor_sync(0xffffffffu, cq1, off);
            }
            if (g == 0) {
                redf(&stat_sum[gn], cs0); redf(&stat_sum[gn + 1], cs1);
                redf(&stat_sq[gn],  cq0); redf(&stat_sq[gn + 1],  cq1);
            }
        }
    }
}

// ---------------- BN finalize + apply ----------------
__global__ void k_bnfin01(const float* __restrict__ g0, const float* __restrict__ b0,
                          const float* __restrict__ g1, const float* __restrict__ b1) {
    int w = threadIdx.x >> 7;
    int c = threadIdx.x & 127;
    const float* g = w ? g1 : g0;
    const float* b = w ? b1 : b0;
    float mean = g_sum[w][c] * (1.f / NN);
    float var  = g_sumsq[w][c] * (1.f / NN) - mean * mean;
    float a = g[c] * rsqrtf(var + 1e-5f);
    g_bnA[w][c] = a;
    g_bnB[w][c] = b[c] - mean * a;
}

__global__ void k_bnfin(int which, const float* __restrict__ g, const float* __restrict__ b) {
    int c = threadIdx.x;
    float mean = g_sum[which][c] * (1.f / NN);
    float var  = g_sumsq[which][c] * (1.f / NN) - mean * mean;
    float a = g[c] * rsqrtf(var + 1e-5f);
    g_bnA[which][c] = a;
    g_bnB[which][c] = b[c] - mean * a;
}

__global__ void k_combine(const float* __restrict__ xl, const float* __restrict__ xa,
                          float* __restrict__ hc) {
    size_t i = (size_t)blockIdx.x * blockDim.x + threadIdx.x;
    if (i >= (size_t)NN * 32) return;
    int c4 = (int)(i & 31);
    float4 xlv = ((const float4*)xl)[i];
    float4 xav = ((const float4*)xa)[i];
    float4 a0 = *(const float4*)&g_bnA[0][c4 * 4];
    float4 b0 = *(const float4*)&g_bnB[0][c4 * 4];
    float4 a1 = *(const float4*)&g_bnA[1][c4 * 4];
    float4 b1 = *(const float4*)&g_bnB[1][c4 * 4];
    float4 o;
    o.x = a0.x * xlv.x + b0.x + a1.x * xav.x + b1.x;
    o.y = a0.y * xlv.y + b0.y + a1.y * xav.y + b1.y;
    o.z = a0.z * xlv.z + b0.z + a1.z * xav.z + b1.z;
    o.w = a0.w * xlv.w + b0.w + a1.w * xav.w + b1.w;
    ((float4*)hc)[i] = o;
}

__global__ void k_apply(const float* __restrict__ hc, float* __restrict__ out) {
    size_t i = (size_t)blockIdx.x * blockDim.x + threadIdx.x;
    if (i >= (size_t)NN * 32) return;
    int c4 = (int)(i & 31);
    float4 xv = ((const float4*)hc)[i];
    float4 a2 = *(const float4*)&g_bnA[2][c4 * 4];
    float4 b2 = *(const float4*)&g_bnB[2][c4 * 4];
    float4 o;
    o.x = a2.x * xv.x + b2.x;
    o.y = a2.y * xv.y + b2.y;
    o.z = a2.z * xv.z + b2.z;
    o.w = a2.w * xv.w + b2.w;
    ((float4*)out)[i] = o;
}

// ---------------- launcher ----------------
extern "C" void kernel_launch(void* const* d_in, const int* in_sizes, int n_in,
                              void* d_out, int out_size) {
    const float* h      = (const float*)d_in[0];
    const float* eattr  = (const float*)d_in[1];
    const int*   src    = (const int*)d_in[2];
    const int*   dst    = (const int*)d_in[3];
    const float* gin_w1 = (const float*)d_in[4];
    const float* gin_b1 = (const float*)d_in[5];
    const float* gin_w2 = (const float*)d_in[6];
    const float* gin_b2 = (const float*)d_in[7];
    const float* wq = (const float*)d_in[8];
    const float* bq = (const float*)d_in[9];
    const float* wk = (const float*)d_in[10];
    const float* bk = (const float*)d_in[11];
    const float* wv = (const float*)d_in[12];
    const float* bv = (const float*)d_in[13];
    const float* nl_g = (const float*)d_in[14];
    const float* nl_b = (const float*)d_in[15];
    const float* na_g = (const float*)d_in[16];
    const float* na_b = (const float*)d_in[17];
    const float* no_g = (const float*)d_in[18];
    const float* no_b = (const float*)d_in[19];
    const float* ffn1_w = (const float*)d_in[20];
    const float* ffn1_b = (const float*)d_in[21];
    const float* ffn2_w = (const float*)d_in[22];
    const float* ffn2_b = (const float*)d_in[23];

    float* out_hc = (float*)d_out;
    float* out_ea = (float*)d_out + (size_t)NN * HH;

    float *p_buf1, *p_agg, *p_q, *p_k, *p_v, *p_ao, *p_hc, *p_sum, *p_sumsq;
    int *p_cnt_s, *p_cnt_d, *p_fill_s, *p_fill_d, *p_rp_s, *p_rp_d, *p_bsum;
    int2 *p_eps, *p_epd;
    cudaGetSymbolAddress((void**)&p_buf1, g_buf1);
    cudaGetSymbolAddress((void**)&p_agg,  g_agg);
    cudaGetSymbolAddress((void**)&p_q,    g_q);
    cudaGetSymbolAddress((void**)&p_k,    g_k);
    cudaGetSymbolAddress((void**)&p_v,    g_v);
    cudaGetSymbolAddress((void**)&p_ao,   g_ao);
    cudaGetSymbolAddress((void**)&p_hc,   g_hc);
    cudaGetSymbolAddress((void**)&p_sum,  g_sum);
    cudaGetSymbolAddress((void**)&p_sumsq, g_sumsq);
    cudaGetSymbolAddress((void**)&p_cnt_s, g_cnt_s);
    cudaGetSymbolAddress((void**)&p_cnt_d, g_cnt_d);
    cudaGetSymbolAddress((void**)&p_fill_s, g_fill_s);
    cudaGetSymbolAddress((void**)&p_fill_d, g_fill_d);
    cudaGetSymbolAddress((void**)&p_rp_s, g_rp_s);
    cudaGetSymbolAddress((void**)&p_rp_d, g_rp_d);
    cudaGetSymbolAddress((void**)&p_bsum, g_bsum);
    cudaGetSymbolAddress((void**)&p_eps, g_eps);
    cudaGetSymbolAddress((void**)&p_epd, g_epd);

    static cudaStream_t s2 = nullptr;
    static cudaEvent_t ev_fork = nullptr, ev_csr = nullptr, ev_join = nullptr;
    if (s2 == nullptr) {
        cudaStreamCreateWithFlags(&s2, cudaStreamNonBlocking);
        cudaEventCreateWithFlags(&ev_fork, cudaEventDisableTiming);
        cudaEventCreateWithFlags(&ev_csr,  cudaEventDisableTiming);
        cudaEventCreateWithFlags(&ev_join, cudaEventDisableTiming);
    }

    const int EB = (EE + 255) / 256;        // edge-parallel blocks
    const int NB = (NN + 7) / 8;            // warp-per-node blocks
    const int MB = (NN + 127) / 128;        // gemm row tiles
    const int SG = (NN + 1024) / 1024;      // scan blocks (covers NN+1)

    cudaMemsetAsync(p_cnt_s, 0, NN * sizeof(int));
    cudaMemsetAsync(p_cnt_d, 0, NN * sizeof(int));
    cudaMemsetAsync(p_fill_s, 0, NN * sizeof(int));
    cudaMemsetAsync(p_fill_d, 0, NN * sizeof(int));
    cudaMemsetAsync(p_sum, 0, 3 * HH * sizeof(float));
    cudaMemsetAsync(p_sumsq, 0, 3 * HH * sizeof(float));

    // fork: QKV GEMMs need only h — start immediately on s2 while main builds CSR
    cudaEventRecord(ev_fork, 0);
    cudaStreamWaitEvent(s2, ev_fork, 0);
    k_gemm_tc<<<dim3(MB, 1), 256, 0, s2>>>(h, wq, bq, nullptr, p_q,
                                           NN, HH, HH, 0.25f, 0, nullptr, nullptr);
    k_gemm_tc<<<dim3(MB, 1), 256, 0, s2>>>(h, wk, bk, nullptr, p_k,
                                           NN, HH, HH, 1.f, 0, nullptr, nullptr);
    k_gemm_tc<<<dim3(MB, 1), 256, 0, s2>>>(h, wv, bv, nullptr, p_v,
                                           NN, HH, HH, 1.f, 0, nullptr, nullptr);

    // main: CSR build (both directions)
    k_hist<<<EB, 256>>>(src, dst, p_cnt_s, p_cnt_d);
    k_scan_block<<<SG, 1024>>>(p_cnt_s, p_rp_s, &p_bsum[0]);
    k_scan_block<<<SG, 1024>>>(p_cnt_d, p_rp_d, &p_bsum[64]);
    k_scan_tops<<<1, 32>>>(&p_bsum[0], SG);
    k_scan_tops<<<1, 32>>>(&p_bsum[64], SG);
    k_scan_add<<<SG, 1024>>>(p_rp_s, &p_bsum[0]);
    k_scan_add<<<SG, 1024>>>(p_rp_d, &p_bsum[64]);
    k_scatter<<<EB, 256>>>(src, dst, p_rp_s, p_rp_d, p_fill_s, p_fill_d, p_eps, p_epd);
    cudaEventRecord(ev_csr, 0);

    // s2: fused attention (after QKV + CSR)
    cudaStreamWaitEvent(s2, ev_csr, 0);
    k_attn_csr<<<NB, 256, 0, s2>>>(h, p_q, p_k, p_v, p_rp_s, p_eps,
                                   p_ao, &p_sum[1 * HH], &p_sumsq[1 * HH]);
    cudaEventRecord(ev_join, s2);

    // main: GINE aggregate + GIN MLP (stats set 0 fused in second GEMM)
    k_agg_csr<<<NB, 256>>>(h, eattr, p_rp_d, p_epd, p_agg, out_ea);
    k_gemm_tc<<<dim3(MB, 1), 256>>>(p_agg, gin_w1, gin_b1, nullptr, p_buf1,
                                    NN, HH, HH, 1.f, 1, nullptr, nullptr);
    k_gemm_tc<<<dim3(MB, 1), 256>>>(p_buf1, gin_w2, gin_b2, h, p_agg,
                                    NN, HH, HH, 1.f, 0, &p_sum[0 * HH], &p_sumsq[0 * HH]);

    // join
    cudaStreamWaitEvent(0, ev_join, 0);

    // finalize BNs 0/1, combine, FFN, BN2, output
    k_bnfin01<<<1, 256>>>(nl_g, nl_b, na_g, na_b);
    k_combine<<<(NN * 32 + 255) / 256, 256>>>(p_agg, p_ao, p_hc);
    k_gemm_tc<<<dim3(MB, 2), 256>>>(p_hc, ffn1_w, ffn1_b, nullptr, p_buf1,
                                    NN, 256, HH, 1.f, 1, nullptr, nullptr);
    k_gemm_tc<<<dim3(MB, 1), 256>>>(p_buf1, ffn2_w, ffn2_b, p_hc, p_hc,
                                    NN, HH, 256, 1.f, 0, &p_sum[2 * HH], &p_sumsq[2 * HH]);
    k_bnfin<<<1, 128>>>(2, no_g, no_b);
    k_apply<<<(NN * 32 + 255) / 256, 256>>>(p_hc, out_hc);
}